// round 1
// baseline (speedup 1.0000x reference)
#include <cuda_runtime.h>
#include <cuda_bf16.h>
#include <math.h>

// Problem constants
#define BATCH   4
#define TSEQ    1024
#define DFEAT   1024
#define NQV     2048
#define MROWS   (BATCH * TSEQ)   // 4096
#define HPS     4
#define C0      21
#define C1      41
#define HALF0   10
#define HALF1   20
#define NLOG    248              // 4*21 + 4*41
#define NLOGPAD 256

// Scratch (no cudaMalloc allowed)
__device__ float g_qv[(size_t)MROWS * NQV];     // [4096, 2048]: cols 0..1023 = relu(q), 1024.. = v
__device__ float g_w2[(size_t)DFEAT * NLOGPAD]; // packed [1024, 256] (cols 248..255 zero)
__device__ float g_attn[(size_t)MROWS * NLOG];  // [bt][h][62] (21 scale0 + 41 scale1), pre-scaled by sw
__device__ float g_x[(size_t)MROWS * DFEAT];    // mixed output before W_out

// ---------------------------------------------------------------------------
// Pack W2_0 [1024,84] and W2_1 [1024,164] into one padded [1024,256] buffer
// ---------------------------------------------------------------------------
__global__ void pack_w2_kernel(const float* __restrict__ w20, const float* __restrict__ w21) {
    int idx = blockIdx.x * blockDim.x + threadIdx.x;   // 0 .. 1024*256-1
    int k = idx >> 8;
    int j = idx & 255;
    float v = 0.f;
    if (j < 84)       v = w20[k * 84 + j];
    else if (j < 248) v = w21[k * 164 + (j - 84)];
    g_w2[idx] = v;
}

// ---------------------------------------------------------------------------
// Generic fp32 GEMM: C[M,N] = A[M,K] @ B[K,N], row-major, M%128==0, N%128==0,
// K%16==0. relu applied to output cols < relu_cols.
// 128x128 block tile, BK=16, 256 threads, 8x8 per thread.
// ---------------------------------------------------------------------------
__global__ __launch_bounds__(256, 2) void gemm128(
    const float* __restrict__ A, const float* __restrict__ B, float* __restrict__ C,
    int M, int N, int K, int relu_cols)
{
    __shared__ float As[16][132];   // transposed A tile, padded
    __shared__ float Bs[16][128];

    const int tid = threadIdx.x;
    const int tx = tid & 15;
    const int ty = tid >> 4;
    const int rowBase = blockIdx.y * 128;
    const int colBase = blockIdx.x * 128;

    float acc[8][8];
#pragma unroll
    for (int i = 0; i < 8; i++)
#pragma unroll
        for (int j = 0; j < 8; j++) acc[i][j] = 0.f;

    for (int k0 = 0; k0 < K; k0 += 16) {
        // load A tile (128 rows x 16 cols), store transposed
#pragma unroll
        for (int i = 0; i < 2; i++) {
            int v = tid + i * 256;          // 0..511 vec4 ids
            int ar = v >> 2;                // 0..127
            int ac = (v & 3) * 4;           // 0,4,8,12
            float4 av = *(const float4*)(A + (size_t)(rowBase + ar) * K + k0 + ac);
            As[ac + 0][ar] = av.x;
            As[ac + 1][ar] = av.y;
            As[ac + 2][ar] = av.z;
            As[ac + 3][ar] = av.w;
        }
        // load B tile (16 rows x 128 cols)
#pragma unroll
        for (int i = 0; i < 2; i++) {
            int v = tid + i * 256;
            int br = v >> 5;                // 0..15
            int bc = (v & 31) * 4;          // 0..124
            *(float4*)(&Bs[br][bc]) = *(const float4*)(B + (size_t)(k0 + br) * N + colBase + bc);
        }
        __syncthreads();

#pragma unroll
        for (int kk = 0; kk < 16; kk++) {
            float a[8], b[8];
            *(float4*)(a)     = *(const float4*)(&As[kk][ty * 8]);
            *(float4*)(a + 4) = *(const float4*)(&As[kk][ty * 8 + 4]);
            *(float4*)(b)     = *(const float4*)(&Bs[kk][tx * 8]);
            *(float4*)(b + 4) = *(const float4*)(&Bs[kk][tx * 8 + 4]);
#pragma unroll
            for (int i = 0; i < 8; i++)
#pragma unroll
                for (int j = 0; j < 8; j++)
                    acc[i][j] += a[i] * b[j];
        }
        __syncthreads();
    }

    // epilogue
#pragma unroll
    for (int i = 0; i < 8; i++) {
        size_t r = (size_t)(rowBase + ty * 8 + i);
        int cb = colBase + tx * 8;
        float o[8];
#pragma unroll
        for (int j = 0; j < 8; j++) {
            float v = acc[i][j];
            if (cb + j < relu_cols) v = fmaxf(v, 0.f);
            o[j] = v;
        }
        *(float4*)(C + r * N + cb)     = *(float4*)(o);
        *(float4*)(C + r * N + cb + 4) = *(float4*)(o + 4);
    }
}

// ---------------------------------------------------------------------------
// Logits + per-head softmax + scale-weight: one block per 16 bt rows.
// Computes logits[16,248] = relu(q)[16,1024] @ g_w2[1024,256], softmaxes per
// (scale,head) group, multiplies by softmax(scale_weights)[scale], writes
// g_attn[bt][h][62].
// ---------------------------------------------------------------------------
__global__ __launch_bounds__(256) void logits_kernel(const float* __restrict__ sweights) {
    __shared__ float sm[8192 + 512];
    float* w2s = sm;           // [32][256]
    float* qs  = sm + 8192;    // [16][32]

    const int row0 = blockIdx.x * 16;
    const int tid = threadIdx.x;
    const int jx = tid & 15;   // col group
    const int ry = tid >> 4;   // row 0..15

    float acc[16];
#pragma unroll
    for (int i = 0; i < 16; i++) acc[i] = 0.f;

    for (int kt = 0; kt < 32; kt++) {
        if (tid < 128) {
            int r = tid >> 3;
            int kc = (tid & 7) * 4;
            *(float4*)(qs + r * 32 + kc) =
                *(const float4*)(g_qv + (size_t)(row0 + r) * NQV + kt * 32 + kc);
        }
#pragma unroll
        for (int i = 0; i < 8; i++) {
            int v = tid + i * 256;
            int kr = v >> 6;             // 0..31
            int kc = (v & 63) * 4;       // 0..252
            *(float4*)(w2s + kr * 256 + kc) =
                *(const float4*)(g_w2 + (size_t)(kt * 32 + kr) * 256 + kc);
        }
        __syncthreads();

#pragma unroll
        for (int kk = 0; kk < 32; kk++) {
            float qb = qs[ry * 32 + kk];
#pragma unroll
            for (int q = 0; q < 4; q++) {
                float4 w = *(const float4*)(w2s + kk * 256 + jx * 4 + q * 64);
                acc[q * 4 + 0] += qb * w.x;
                acc[q * 4 + 1] += qb * w.y;
                acc[q * 4 + 2] += qb * w.z;
                acc[q * 4 + 3] += qb * w.w;
            }
        }
        __syncthreads();
    }

    // dump logits to smem (reuse w2s region)
    float* lb = sm;   // [16][256]
#pragma unroll
    for (int q = 0; q < 4; q++)
#pragma unroll
        for (int i = 0; i < 4; i++)
            lb[ry * 256 + jx * 4 + q * 64 + i] = acc[q * 4 + i];
    __syncthreads();

    // group reductions: 16 rows x 8 groups (4 heads scale0, 4 heads scale1)
    float* gm = sm + 8192;          // [16][8]
    float* gs = sm + 8192 + 128;    // [16][8]
    if (tid < 128) {
        int r = tid >> 3, g = tid & 7;
        int base, len;
        if (g < 4) { base = g * 21; len = 21; }
        else       { base = 84 + (g - 4) * 41; len = 41; }
        float m = -1e30f;
        for (int c = 0; c < len; c++) m = fmaxf(m, lb[r * 256 + base + c]);
        float s = 0.f;
        for (int c = 0; c < len; c++) s += expf(lb[r * 256 + base + c] - m);
        gm[r * 8 + g] = m;
        gs[r * 8 + g] = s;
    }
    __syncthreads();

    // softmax of scale weights (2 values)
    float s0 = sweights[0], s1 = sweights[1];
    float mm = fmaxf(s0, s1);
    float e0 = expf(s0 - mm), e1 = expf(s1 - mm);
    float inv = 1.f / (e0 + e1);
    float sw0 = e0 * inv, sw1 = e1 * inv;

#pragma unroll
    for (int q = 0; q < 4; q++)
#pragma unroll
        for (int i = 0; i < 4; i++) {
            int col = jx * 4 + q * 64 + i;
            if (col >= NLOG) continue;
            int h, cpos, g;
            float sw;
            if (col < 84) { h = col / 21; cpos = col % 21; g = h; sw = sw0; }
            else {
                int cc = col - 84;
                h = cc / 41; cpos = 21 + cc % 41; g = 4 + h; sw = sw1;
            }
            float a = expf(acc[q * 4 + i] - gm[ry * 8 + g]) / gs[ry * 8 + g] * sw;
            g_attn[(size_t)(row0 + ry) * NLOG + h * 62 + cpos] = a;
        }
}

// ---------------------------------------------------------------------------
// Sliding-window weighted sum: x[bt, :] = sum_scales sum_c attn * v[t+c-half]
// One block per (t-tile of 32, 128-wide D slice, batch). v tile cached in smem
// with 20-row halo each side.
// ---------------------------------------------------------------------------
__global__ __launch_bounds__(256) void attn_apply_kernel() {
    __shared__ float vs[72][128];    // rows t0-20 .. t0+51
    __shared__ float as_[32][62];

    const int t0 = blockIdx.x * 32;
    const int by = blockIdx.y;       // 0..7 : D slice (head = by>>1)
    const int b  = blockIdx.z;
    const int h  = by >> 1;
    const int coff = by * 128;
    const int tid = threadIdx.x;

    // load v slice: 72 rows x 128 cols = 2304 float4
#pragma unroll
    for (int i = 0; i < 9; i++) {
        int v = tid + i * 256;
        int row = v >> 5;              // 0..71
        int cv = (v & 31) * 4;
        int gt = t0 - 20 + row;
        float4 val = make_float4(0.f, 0.f, 0.f, 0.f);
        if (gt >= 0 && gt < TSEQ)
            val = *(const float4*)(g_qv + (size_t)(b * TSEQ + gt) * NQV + DFEAT + coff + cv);
        *(float4*)(&vs[row][cv]) = val;
    }
    // load attention weights
    for (int idx = tid; idx < 32 * 62; idx += 256) {
        int tl = idx / 62, c = idx % 62;
        as_[tl][c] = g_attn[(size_t)(b * TSEQ + t0 + tl) * NLOG + h * 62 + c];
    }
    __syncthreads();

    const int d = tid & 127;
    for (int tl = (tid >> 7); tl < 32; tl += 2) {
        float acc = 0.f;
#pragma unroll
        for (int c = 0; c < C0; c++)      // scale 0: row = tl + 10 + c
            acc += as_[tl][c] * vs[tl + 10 + c][d];
#pragma unroll
        for (int c = 0; c < C1; c++)      // scale 1: row = tl + c
            acc += as_[tl][21 + c] * vs[tl + c][d];
        g_x[(size_t)(b * TSEQ + t0 + tl) * DFEAT + coff + d] = acc;
    }
}

// ---------------------------------------------------------------------------
// Launch
// ---------------------------------------------------------------------------
extern "C" void kernel_launch(void* const* d_in, const int* in_sizes, int n_in,
                              void* d_out, int out_size) {
    const float* query    = (const float*)d_in[0];
    // d_in[1] = key (unused), d_in[2] = value (unused)
    const float* W_qv     = (const float*)d_in[3];
    const float* W2_0     = (const float*)d_in[4];
    const float* W2_1     = (const float*)d_in[5];
    const float* sweights = (const float*)d_in[6];
    const float* W_out    = (const float*)d_in[7];
    float* out = (float*)d_out;

    void *qv_p = nullptr, *x_p = nullptr;
    cudaGetSymbolAddress(&qv_p, g_qv);
    cudaGetSymbolAddress(&x_p, g_x);

    // 1) pack W2
    pack_w2_kernel<<<1024, 256>>>(W2_0, W2_1);
    // 2) qv = query @ W_qv, relu on first 1024 cols (q), identity on v
    gemm128<<<dim3(NQV / 128, MROWS / 128), 256>>>(query, W_qv, (float*)qv_p,
                                                   MROWS, NQV, DFEAT, DFEAT);
    // 3) logits + softmax + scale weighting
    logits_kernel<<<MROWS / 16, 256>>>(sweights);
    // 4) sliding-window weighted sum -> g_x
    attn_apply_kernel<<<dim3(TSEQ / 32, 8, BATCH), 256>>>();
    // 5) out = g_x @ W_out
    gemm128<<<dim3(DFEAT / 128, MROWS / 128), 256>>>((const float*)x_p, W_out, out,
                                                     MROWS, DFEAT, DFEAT, 0);
}

// round 3
// speedup vs baseline: 3.1664x; 3.1664x over previous
#include <cuda_runtime.h>
#include <cuda_bf16.h>
#include <math.h>
#include <stdint.h>

// ---------------------------------------------------------------------------
// Problem constants
// ---------------------------------------------------------------------------
#define BATCH   4
#define TSEQ    1024
#define DFEAT   1024
#define NQV     2048
#define MROWS   (BATCH * TSEQ)   // 4096
#define C0      21
#define C1      41
#define NLOG    248
#define NLOGPAD 256

// ---------------------------------------------------------------------------
// Scratch (no cudaMalloc allowed)
// ---------------------------------------------------------------------------
__device__ float g_qtf  [(size_t)MROWS * DFEAT];    // tf32-rounded query
__device__ float g_wqvt [(size_t)NQV * DFEAT];      // W_qv^T  [2048,1024], tf32-rounded
__device__ float g_woutt[(size_t)DFEAT * DFEAT];    // W_out^T [1024,1024], tf32-rounded
__device__ float g_w2t  [(size_t)NLOGPAD * DFEAT];  // packed W2^T [256,1024], tf32-rounded
__device__ float g_qv   [(size_t)MROWS * NQV];      // cols<1024: relu(q) tf32-rounded; >=1024: v
__device__ float g_logits[(size_t)MROWS * NLOGPAD];
__device__ float g_attn [(size_t)MROWS * NLOG];     // [bt][h][62], pre-scaled by sw
__device__ float g_x    [(size_t)MROWS * DFEAT];    // mixed output (tf32-rounded)

// ---------------------------------------------------------------------------
// Helpers
// ---------------------------------------------------------------------------
__device__ __forceinline__ uint32_t smem_u32(const void* p) {
    uint32_t a;
    asm("{ .reg .u64 t; cvta.to.shared.u64 t, %1; cvt.u32.u64 %0, t; }" : "=r"(a) : "l"(p));
    return a;
}
__device__ __forceinline__ float rna_tf32(float x) {
    uint32_t u; asm("cvt.rna.tf32.f32 %0, %1;" : "=r"(u) : "f"(x));
    return __uint_as_float(u);
}
__device__ __forceinline__ void cp_async16(uint32_t dst, const void* src) {
    asm volatile("cp.async.cg.shared.global [%0], [%1], 16;" :: "r"(dst), "l"(src));
}
__device__ __forceinline__ void cp_commit() {
    asm volatile("cp.async.commit_group;" ::: "memory");
}
__device__ __forceinline__ void ldsm4(uint32_t* r, uint32_t addr) {
    asm volatile("ldmatrix.sync.aligned.m8n8.x4.shared.b16 {%0,%1,%2,%3}, [%4];"
        : "=r"(r[0]), "=r"(r[1]), "=r"(r[2]), "=r"(r[3]) : "r"(addr));
}
__device__ __forceinline__ void mma_tf32(float* c, const uint32_t* a, const uint32_t* b) {
    asm volatile("mma.sync.aligned.m16n8k8.row.col.f32.tf32.tf32.f32 "
        "{%0,%1,%2,%3}, {%4,%5,%6,%7}, {%8,%9}, {%0,%1,%2,%3};"
        : "+f"(c[0]), "+f"(c[1]), "+f"(c[2]), "+f"(c[3])
        : "r"(a[0]), "r"(a[1]), "r"(a[2]), "r"(a[3]), "r"(b[0]), "r"(b[1]));
}

// ---------------------------------------------------------------------------
// Prep kernels
// ---------------------------------------------------------------------------
__global__ void round_query_kernel(const float4* __restrict__ in, float4* __restrict__ out, int n4) {
    int i = blockIdx.x * 256 + threadIdx.x;
    if (i < n4) {
        float4 v = in[i];
        v.x = rna_tf32(v.x); v.y = rna_tf32(v.y); v.z = rna_tf32(v.z); v.w = rna_tf32(v.w);
        out[i] = v;
    }
}

// in [K,N] row-major -> out [N,K] row-major, tf32-rounded
__global__ void transpose_round_kernel(const float* __restrict__ in, float* __restrict__ out,
                                       int K, int N) {
    __shared__ float t[32][33];
    int n0 = blockIdx.x * 32, k0 = blockIdx.y * 32;
    int tx = threadIdx.x & 31, ty = threadIdx.x >> 5;
#pragma unroll
    for (int i = 0; i < 4; i++)
        t[ty + i * 8][tx] = in[(size_t)(k0 + ty + i * 8) * N + n0 + tx];
    __syncthreads();
#pragma unroll
    for (int i = 0; i < 4; i++)
        out[(size_t)(n0 + ty + i * 8) * K + k0 + tx] = rna_tf32(t[tx][ty + i * 8]);
}

// pack W2_0 [1024,84], W2_1 [1024,164] -> g_w2t [256,1024] transposed, padded, rounded
__global__ void pack_w2t_kernel(const float* __restrict__ w20, const float* __restrict__ w21) {
    int idx = blockIdx.x * 256 + threadIdx.x;    // 0 .. 256*1024-1
    int n = idx >> 10, k = idx & 1023;
    float v = 0.f;
    if (n < 84)       v = w20[k * 84 + n];
    else if (n < 248) v = w21[k * 164 + (n - 84)];
    g_w2t[idx] = rna_tf32(v);
}

// ---------------------------------------------------------------------------
// tf32 mma.sync GEMM: C[M,N] = A[M,K] @ Bt[N,K]^T
// 128x128 block tile, BK=32, 3-stage cp.async, 8 warps (each m64n32),
// ldmatrix.x4 fragment loads from XOR-swizzled smem.
// Epilogue: cols < relu_cols get relu + tf32-round.
// ---------------------------------------------------------------------------
#define BM 128
#define BN 128
#define BK 32
#define NSTAGE 3
#define STAGE_BYTES (BM * BK * 4 + BN * BK * 4)   // 32768
#define GEMM_SMEM (NSTAGE * STAGE_BYTES)          // 98304

__device__ __forceinline__ void gemm_load_tile(uint32_t stageBase,
                                               const float* Ag, int lda,
                                               const float* Bg, int ldb, int tid) {
    // A: 128 rows x 8 chunks(16B); swizzle chunk ^= row&7
#pragma unroll
    for (int i = 0; i < 4; i++) {
        int cid = tid + i * 256;
        int r = cid >> 3, ch = cid & 7;
        uint32_t dst = stageBase + r * 128 + ((ch ^ (r & 7)) << 4);
        cp_async16(dst, Ag + (size_t)r * lda + ch * 4);
    }
    uint32_t bBase = stageBase + BM * BK * 4;
#pragma unroll
    for (int i = 0; i < 4; i++) {
        int cid = tid + i * 256;
        int r = cid >> 3, ch = cid & 7;
        uint32_t dst = bBase + r * 128 + ((ch ^ (r & 7)) << 4);
        cp_async16(dst, Bg + (size_t)r * ldb + ch * 4);
    }
}

__global__ __launch_bounds__(256, 1)
void gemm_tc_kernel(const float* __restrict__ A, int lda,
                    const float* __restrict__ Bt, int ldb,
                    float* __restrict__ C, int ldc,
                    int K, int relu_cols) {
    extern __shared__ char smem[];
    const uint32_t sb = smem_u32(smem);
    const int tid = threadIdx.x;
    const int lane = tid & 31, warp = tid >> 5;
    const int wm = (warp & 1) * 64;     // warp m offset in tile
    const int wn = (warp >> 1) * 32;    // warp n offset in tile
    const int mBase = blockIdx.y * BM;
    const int nBase = blockIdx.x * BN;
    const int lrow = lane & 7, mat = lane >> 3;

    const float* Abase = A + (size_t)mBase * lda;
    const float* Bbase = Bt + (size_t)nBase * ldb;
    const int NIT = K / BK;

    float acc[4][4][4];
#pragma unroll
    for (int i = 0; i < 4; i++)
#pragma unroll
        for (int j = 0; j < 4; j++)
#pragma unroll
            for (int l = 0; l < 4; l++) acc[i][j][l] = 0.f;

    // prologue: stages 0,1
    gemm_load_tile(sb, Abase, lda, Bbase, ldb, tid); cp_commit();
    gemm_load_tile(sb + STAGE_BYTES, Abase + BK, lda, Bbase + BK, ldb, tid); cp_commit();

    // precomputed ldsm row indices (within tile)
    int arow[4], brow[2];
#pragma unroll
    for (int mt = 0; mt < 4; mt++) arow[mt] = wm + mt * 16 + ((mat & 1) << 3) + lrow;
#pragma unroll
    for (int nb = 0; nb < 2; nb++) brow[nb] = wn + nb * 16 + ((mat >> 1) << 3) + lrow;
    const int achunk = (mat >> 1);   // + 2*kk
    const int bchunk = (mat & 1);    // + 2*kk

    for (int it = 0; it < NIT; it++) {
        int s = it - (it / 3) * 3;
        asm volatile("cp.async.wait_group 1;" ::: "memory");
        __syncthreads();

        uint32_t aTile = sb + s * STAGE_BYTES;
        uint32_t bTile = aTile + BM * BK * 4;

#pragma unroll
        for (int kk = 0; kk < 4; kk++) {
            uint32_t af[4][4], bf[4][2];
#pragma unroll
            for (int mt = 0; mt < 4; mt++) {
                int ch = 2 * kk + achunk;
                uint32_t addr = aTile + arow[mt] * 128 + ((ch ^ (arow[mt] & 7)) << 4);
                ldsm4(af[mt], addr);
            }
#pragma unroll
            for (int nb = 0; nb < 2; nb++) {
                int ch = 2 * kk + bchunk;
                uint32_t addr = bTile + brow[nb] * 128 + ((ch ^ (brow[nb] & 7)) << 4);
                uint32_t r[4];
                ldsm4(r, addr);
                bf[nb * 2][0] = r[0]; bf[nb * 2][1] = r[1];
                bf[nb * 2 + 1][0] = r[2]; bf[nb * 2 + 1][1] = r[3];
            }
#pragma unroll
            for (int mt = 0; mt < 4; mt++)
#pragma unroll
                for (int nt = 0; nt < 4; nt++)
                    mma_tf32(acc[mt][nt], af[mt], bf[nt]);
        }

        // issue loads for it+2 (stage consumed at it-1; all warps past sync)
        if (it + 2 < NIT) {
            int sw = (it + 2) - ((it + 2) / 3) * 3;
            gemm_load_tile(sb + sw * STAGE_BYTES,
                           Abase + (it + 2) * BK, lda, Bbase + (it + 2) * BK, ldb, tid);
        }
        cp_commit();   // always commit to keep group count uniform
    }

    // epilogue
    const int g = lane >> 2, tig = lane & 3;
#pragma unroll
    for (int mt = 0; mt < 4; mt++) {
#pragma unroll
        for (int nt = 0; nt < 4; nt++) {
            int row = mBase + wm + mt * 16 + g;
            int col = nBase + wn + nt * 8 + tig * 2;
            float2 v0 = make_float2(acc[mt][nt][0], acc[mt][nt][1]);
            float2 v1 = make_float2(acc[mt][nt][2], acc[mt][nt][3]);
            if (col < relu_cols) {
                v0.x = rna_tf32(fmaxf(v0.x, 0.f)); v0.y = rna_tf32(fmaxf(v0.y, 0.f));
                v1.x = rna_tf32(fmaxf(v1.x, 0.f)); v1.y = rna_tf32(fmaxf(v1.y, 0.f));
            }
            *(float2*)(C + (size_t)row * ldc + col) = v0;
            *(float2*)(C + (size_t)(row + 8) * ldc + col) = v1;
        }
    }
}

// ---------------------------------------------------------------------------
// Softmax over logits groups -> g_attn (pre-scaled by softmax(scale_weights))
// ---------------------------------------------------------------------------
__global__ void softmax_kernel(const float* __restrict__ sweights) {
    int idx = blockIdx.x * 256 + threadIdx.x;
    if (idx >= MROWS * 8) return;
    int row = idx >> 3, gidx = idx & 7;
    const float* lp = g_logits + (size_t)row * NLOGPAD;
    int base, len, h, cbase;
    if (gidx < 4) { base = gidx * 21;            len = 21; h = gidx;     cbase = 0; }
    else          { base = 84 + (gidx - 4) * 41; len = 41; h = gidx - 4; cbase = 21; }
    float m = -1e30f;
    for (int c = 0; c < len; c++) m = fmaxf(m, lp[base + c]);
    float ssum = 0.f;
    for (int c = 0; c < len; c++) ssum += expf(lp[base + c] - m);
    float s0 = sweights[0], s1 = sweights[1];
    float mm = fmaxf(s0, s1);
    float e0 = expf(s0 - mm), e1 = expf(s1 - mm);
    float sw = ((gidx < 4) ? e0 : e1) / (e0 + e1);
    float inv = sw / ssum;
    float* ap = g_attn + (size_t)row * NLOG + h * 62 + cbase;
    for (int c = 0; c < len; c++) ap[c] = expf(lp[base + c] - m) * inv;
}

// ---------------------------------------------------------------------------
// Sliding-window weighted sum -> g_x (tf32-rounded for the output GEMM)
// ---------------------------------------------------------------------------
__global__ __launch_bounds__(256) void attn_apply_kernel() {
    __shared__ float vs[72][128];
    __shared__ float as_[32][62];

    const int t0 = blockIdx.x * 32;
    const int by = blockIdx.y;       // 0..7 : 128-wide D slice (head = by>>1)
    const int b  = blockIdx.z;
    const int h  = by >> 1;
    const int coff = by * 128;
    const int tid = threadIdx.x;

#pragma unroll
    for (int i = 0; i < 9; i++) {
        int v = tid + i * 256;
        int row = v >> 5;
        int cv = (v & 31) * 4;
        int gt = t0 - 20 + row;
        float4 val = make_float4(0.f, 0.f, 0.f, 0.f);
        if (gt >= 0 && gt < TSEQ)
            val = *(const float4*)(g_qv + (size_t)(b * TSEQ + gt) * NQV + DFEAT + coff + cv);
        *(float4*)(&vs[row][cv]) = val;
    }
    for (int idx = tid; idx < 32 * 62; idx += 256) {
        int tl = idx / 62, c = idx % 62;
        as_[tl][c] = g_attn[(size_t)(b * TSEQ + t0 + tl) * NLOG + h * 62 + c];
    }
    __syncthreads();

    const int d = tid & 127;
    for (int tl = (tid >> 7); tl < 32; tl += 2) {
        float acc = 0.f;
#pragma unroll
        for (int c = 0; c < C0; c++)
            acc += as_[tl][c] * vs[tl + 10 + c][d];
#pragma unroll
        for (int c = 0; c < C1; c++)
            acc += as_[tl][21 + c] * vs[tl + c][d];
        g_x[(size_t)(b * TSEQ + t0 + tl) * DFEAT + coff + d] = rna_tf32(acc);
    }
}

// ---------------------------------------------------------------------------
// Launch
// ---------------------------------------------------------------------------
extern "C" void kernel_launch(void* const* d_in, const int* in_sizes, int n_in,
                              void* d_out, int out_size) {
    const float* query    = (const float*)d_in[0];
    // d_in[1]=key, d_in[2]=value: unused by reference
    const float* W_qv     = (const float*)d_in[3];
    const float* W2_0     = (const float*)d_in[4];
    const float* W2_1     = (const float*)d_in[5];
    const float* sweights = (const float*)d_in[6];
    const float* W_out    = (const float*)d_in[7];
    float* out = (float*)d_out;

    cudaFuncSetAttribute(gemm_tc_kernel, cudaFuncAttributeMaxDynamicSharedMemorySize, GEMM_SMEM);

    void *qtf_p = nullptr, *wqvt_p = nullptr, *woutt_p = nullptr, *w2t_p = nullptr;
    void *qv_p = nullptr, *logits_p = nullptr, *x_p = nullptr;
    cudaGetSymbolAddress(&qtf_p, g_qtf);
    cudaGetSymbolAddress(&wqvt_p, g_wqvt);
    cudaGetSymbolAddress(&woutt_p, g_woutt);
    cudaGetSymbolAddress(&w2t_p, g_w2t);
    cudaGetSymbolAddress(&qv_p, g_qv);
    cudaGetSymbolAddress(&logits_p, g_logits);
    cudaGetSymbolAddress(&x_p, g_x);

    // 1) prep
    round_query_kernel<<<(MROWS * DFEAT / 4 + 255) / 256, 256>>>(
        (const float4*)query, (float4*)qtf_p, MROWS * DFEAT / 4);
    transpose_round_kernel<<<dim3(NQV / 32, DFEAT / 32), 256>>>(W_qv, (float*)wqvt_p, DFEAT, NQV);
    transpose_round_kernel<<<dim3(DFEAT / 32, DFEAT / 32), 256>>>(W_out, (float*)woutt_p, DFEAT, DFEAT);
    pack_w2t_kernel<<<NLOGPAD * DFEAT / 256, 256>>>(W2_0, W2_1);

    // 2) qv = query @ W_qv  (relu + tf32-round on q half)
    gemm_tc_kernel<<<dim3(NQV / BN, MROWS / BM), 256, GEMM_SMEM>>>(
        (const float*)qtf_p, DFEAT, (const float*)wqvt_p, DFEAT,
        (float*)qv_p, NQV, DFEAT, DFEAT);

    // 3) logits = relu(q) @ W2
    gemm_tc_kernel<<<dim3(NLOGPAD / BN, MROWS / BM), 256, GEMM_SMEM>>>(
        (const float*)qv_p, NQV, (const float*)w2t_p, DFEAT,
        (float*)logits_p, NLOGPAD, DFEAT, 0);

    // 4) per-group softmax + scale weighting
    softmax_kernel<<<(MROWS * 8 + 255) / 256, 256>>>(sweights);

    // 5) sliding-window weighted sum
    attn_apply_kernel<<<dim3(TSEQ / 32, 8, BATCH), 256>>>();

    // 6) out = g_x @ W_out
    gemm_tc_kernel<<<dim3(DFEAT / BN, MROWS / BM), 256, GEMM_SMEM>>>(
        (const float*)x_p, DFEAT, (const float*)woutt_p, DFEAT,
        out, DFEAT, DFEAT, 0);
}

// round 4
// speedup vs baseline: 3.4347x; 1.0847x over previous
#include <cuda_runtime.h>
#include <cuda_bf16.h>
#include <math.h>
#include <stdint.h>

// ---------------------------------------------------------------------------
// Problem constants
// ---------------------------------------------------------------------------
#define BATCH   4
#define TSEQ    1024
#define DFEAT   1024
#define NQV     2048
#define MROWS   (BATCH * TSEQ)   // 4096
#define C0      21
#define C1      41
#define NLOG    248
#define NLOGPAD 256

// ---------------------------------------------------------------------------
// Scratch (no cudaMalloc allowed)
// ---------------------------------------------------------------------------
__device__ float g_qtf  [(size_t)MROWS * DFEAT];    // tf32-rounded query
__device__ float g_wqvt [(size_t)NQV * DFEAT];      // W_qv^T  [2048,1024], tf32-rounded
__device__ float g_woutt[(size_t)DFEAT * DFEAT];    // W_out^T [1024,1024], tf32-rounded
__device__ float g_w2t  [(size_t)NLOGPAD * DFEAT];  // packed W2^T [256,1024], tf32-rounded
__device__ float g_qv   [(size_t)MROWS * NQV];      // cols<1024: relu(q) tf32-rounded; >=1024: v
__device__ float g_logits[(size_t)MROWS * NLOGPAD];
__device__ float g_attn [(size_t)MROWS * NLOG];     // [bt][h][62], pre-scaled by sw
__device__ float g_x    [(size_t)MROWS * DFEAT];    // mixed output (tf32-rounded)

// ---------------------------------------------------------------------------
// Helpers
// ---------------------------------------------------------------------------
__device__ __forceinline__ uint32_t smem_u32(const void* p) {
    uint32_t a;
    asm("{ .reg .u64 t; cvta.to.shared.u64 t, %1; cvt.u32.u64 %0, t; }" : "=r"(a) : "l"(p));
    return a;
}
__device__ __forceinline__ float rna_tf32(float x) {
    uint32_t u; asm("cvt.rna.tf32.f32 %0, %1;" : "=r"(u) : "f"(x));
    return __uint_as_float(u);
}
__device__ __forceinline__ void cp_async16(uint32_t dst, const void* src) {
    asm volatile("cp.async.cg.shared.global [%0], [%1], 16;" :: "r"(dst), "l"(src));
}
__device__ __forceinline__ void cp_commit() {
    asm volatile("cp.async.commit_group;" ::: "memory");
}
__device__ __forceinline__ void ldsm4(uint32_t* r, uint32_t addr) {
    asm volatile("ldmatrix.sync.aligned.m8n8.x4.shared.b16 {%0,%1,%2,%3}, [%4];"
        : "=r"(r[0]), "=r"(r[1]), "=r"(r[2]), "=r"(r[3]) : "r"(addr));
}
__device__ __forceinline__ void mma_tf32(float* c, const uint32_t* a, const uint32_t* b) {
    asm volatile("mma.sync.aligned.m16n8k8.row.col.f32.tf32.tf32.f32 "
        "{%0,%1,%2,%3}, {%4,%5,%6,%7}, {%8,%9}, {%0,%1,%2,%3};"
        : "+f"(c[0]), "+f"(c[1]), "+f"(c[2]), "+f"(c[3])
        : "r"(a[0]), "r"(a[1]), "r"(a[2]), "r"(a[3]), "r"(b[0]), "r"(b[1]));
}

// ---------------------------------------------------------------------------
// Prep kernels
// ---------------------------------------------------------------------------
__global__ void round_query_kernel(const float4* __restrict__ in, float4* __restrict__ out, int n4) {
    int i = blockIdx.x * 256 + threadIdx.x;
    if (i < n4) {
        float4 v = in[i];
        v.x = rna_tf32(v.x); v.y = rna_tf32(v.y); v.z = rna_tf32(v.z); v.w = rna_tf32(v.w);
        out[i] = v;
    }
}

// in [K,N] row-major -> out [N,K] row-major, tf32-rounded
__global__ void transpose_round_kernel(const float* __restrict__ in, float* __restrict__ out,
                                       int K, int N) {
    __shared__ float t[32][33];
    int n0 = blockIdx.x * 32, k0 = blockIdx.y * 32;
    int tx = threadIdx.x & 31, ty = threadIdx.x >> 5;
#pragma unroll
    for (int i = 0; i < 4; i++)
        t[ty + i * 8][tx] = in[(size_t)(k0 + ty + i * 8) * N + n0 + tx];
    __syncthreads();
#pragma unroll
    for (int i = 0; i < 4; i++)
        out[(size_t)(n0 + ty + i * 8) * K + k0 + tx] = rna_tf32(t[tx][ty + i * 8]);
}

// pack W2_0 [1024,84], W2_1 [1024,164] -> g_w2t [256,1024] transposed, padded, rounded
__global__ void pack_w2t_kernel(const float* __restrict__ w20, const float* __restrict__ w21) {
    int idx = blockIdx.x * 256 + threadIdx.x;    // 0 .. 256*1024-1
    int n = idx >> 10, k = idx & 1023;
    float v = 0.f;
    if (n < 84)       v = w20[k * 84 + n];
    else if (n < 248) v = w21[k * 164 + (n - 84)];
    g_w2t[idx] = rna_tf32(v);
}

// ---------------------------------------------------------------------------
// tf32 mma.sync GEMM: C[M,N] = A[M,K] @ Bt[N,K]^T
// 128(M) x 256(N) block tile, BK=32, 3-stage cp.async, 8 warps (each m64n64),
// ldmatrix.x4 fragment loads from XOR-swizzled smem.
// Epilogue: cols < relu_cols get relu + tf32-round.
// ---------------------------------------------------------------------------
#define BM 128
#define BN 256
#define BK 32
#define NSTAGE 3
#define STAGE_BYTES ((BM + BN) * BK * 4)          // 49152
#define GEMM_SMEM (NSTAGE * STAGE_BYTES)          // 147456

__device__ __forceinline__ void gemm_load_tile(uint32_t stageBase,
                                               const float* Ag, int lda,
                                               const float* Bg, int ldb, int tid) {
    // A: 128 rows x 8 chunks(16B); swizzle chunk ^= row&7
#pragma unroll
    for (int i = 0; i < 4; i++) {
        int cid = tid + i * 256;
        int r = cid >> 3, ch = cid & 7;
        uint32_t dst = stageBase + r * 128 + ((ch ^ (r & 7)) << 4);
        cp_async16(dst, Ag + (size_t)r * lda + ch * 4);
    }
    uint32_t bBase = stageBase + BM * BK * 4;
    // B: 256 rows x 8 chunks
#pragma unroll
    for (int i = 0; i < 8; i++) {
        int cid = tid + i * 256;
        int r = cid >> 3, ch = cid & 7;
        uint32_t dst = bBase + r * 128 + ((ch ^ (r & 7)) << 4);
        cp_async16(dst, Bg + (size_t)r * ldb + ch * 4);
    }
}

__global__ __launch_bounds__(256, 1)
void gemm_tc_kernel(const float* __restrict__ A, int lda,
                    const float* __restrict__ Bt, int ldb,
                    float* __restrict__ C, int ldc,
                    int K, int relu_cols) {
    extern __shared__ char smem[];
    const uint32_t sb = smem_u32(smem);
    const int tid = threadIdx.x;
    const int lane = tid & 31, warp = tid >> 5;
    const int wm = (warp & 1) * 64;     // warp m offset
    const int wn = (warp >> 1) * 64;    // warp n offset
    const int mBase = blockIdx.y * BM;
    const int nBase = blockIdx.x * BN;
    const int lrow = lane & 7, mat = lane >> 3;

    const float* Abase = A + (size_t)mBase * lda;
    const float* Bbase = Bt + (size_t)nBase * ldb;
    const int NIT = K / BK;

    float acc[4][8][4];
#pragma unroll
    for (int i = 0; i < 4; i++)
#pragma unroll
        for (int j = 0; j < 8; j++)
#pragma unroll
            for (int l = 0; l < 4; l++) acc[i][j][l] = 0.f;

    // prologue: stages 0,1
    gemm_load_tile(sb, Abase, lda, Bbase, ldb, tid); cp_commit();
    gemm_load_tile(sb + STAGE_BYTES, Abase + BK, lda, Bbase + BK, ldb, tid); cp_commit();

    // ldsm row indices (within tile)
    int arow[4], brow[4];
#pragma unroll
    for (int mt = 0; mt < 4; mt++) arow[mt] = wm + mt * 16 + ((mat & 1) << 3) + lrow;
#pragma unroll
    for (int nb = 0; nb < 4; nb++) brow[nb] = wn + nb * 16 + ((mat >> 1) << 3) + lrow;
    const int achunk = (mat >> 1);   // + 2*kk
    const int bchunk = (mat & 1);    // + 2*kk

    for (int it = 0; it < NIT; it++) {
        int s = it - (it / 3) * 3;
        asm volatile("cp.async.wait_group 1;" ::: "memory");
        __syncthreads();

        uint32_t aTile = sb + s * STAGE_BYTES;
        uint32_t bTile = aTile + BM * BK * 4;

#pragma unroll
        for (int kk = 0; kk < 4; kk++) {
            uint32_t af[4][4], bf[8][2];
#pragma unroll
            for (int mt = 0; mt < 4; mt++) {
                int ch = 2 * kk + achunk;
                uint32_t addr = aTile + arow[mt] * 128 + ((ch ^ (arow[mt] & 7)) << 4);
                ldsm4(af[mt], addr);
            }
#pragma unroll
            for (int nb = 0; nb < 4; nb++) {
                int ch = 2 * kk + bchunk;
                uint32_t addr = bTile + brow[nb] * 128 + ((ch ^ (brow[nb] & 7)) << 4);
                uint32_t r[4];
                ldsm4(r, addr);
                bf[nb * 2][0] = r[0]; bf[nb * 2][1] = r[1];
                bf[nb * 2 + 1][0] = r[2]; bf[nb * 2 + 1][1] = r[3];
            }
#pragma unroll
            for (int mt = 0; mt < 4; mt++)
#pragma unroll
                for (int nt = 0; nt < 8; nt++)
                    mma_tf32(acc[mt][nt], af[mt], bf[nt]);
        }

        if (it + 2 < NIT) {
            int sw = (it + 2) - ((it + 2) / 3) * 3;
            gemm_load_tile(sb + sw * STAGE_BYTES,
                           Abase + (it + 2) * BK, lda, Bbase + (it + 2) * BK, ldb, tid);
        }
        cp_commit();   // keep group count uniform
    }

    // epilogue
    const int g = lane >> 2, tig = lane & 3;
#pragma unroll
    for (int mt = 0; mt < 4; mt++) {
#pragma unroll
        for (int nt = 0; nt < 8; nt++) {
            int row = mBase + wm + mt * 16 + g;
            int col = nBase + wn + nt * 8 + tig * 2;
            float2 v0 = make_float2(acc[mt][nt][0], acc[mt][nt][1]);
            float2 v1 = make_float2(acc[mt][nt][2], acc[mt][nt][3]);
            if (col < relu_cols) {
                v0.x = rna_tf32(fmaxf(v0.x, 0.f)); v0.y = rna_tf32(fmaxf(v0.y, 0.f));
                v1.x = rna_tf32(fmaxf(v1.x, 0.f)); v1.y = rna_tf32(fmaxf(v1.y, 0.f));
            }
            *(float2*)(C + (size_t)row * ldc + col) = v0;
            *(float2*)(C + (size_t)(row + 8) * ldc + col) = v1;
        }
    }
}

// ---------------------------------------------------------------------------
// Softmax over logits groups -> g_attn (pre-scaled by softmax(scale_weights))
// ---------------------------------------------------------------------------
__global__ void softmax_kernel(const float* __restrict__ sweights) {
    int idx = blockIdx.x * 256 + threadIdx.x;
    if (idx >= MROWS * 8) return;
    int row = idx >> 3, gidx = idx & 7;
    const float* lp = g_logits + (size_t)row * NLOGPAD;
    int base, len, h, cbase;
    if (gidx < 4) { base = gidx * 21;            len = 21; h = gidx;     cbase = 0; }
    else          { base = 84 + (gidx - 4) * 41; len = 41; h = gidx - 4; cbase = 21; }
    float m = -1e30f;
    for (int c = 0; c < len; c++) m = fmaxf(m, lp[base + c]);
    float ssum = 0.f;
    for (int c = 0; c < len; c++) ssum += expf(lp[base + c] - m);
    float s0 = sweights[0], s1 = sweights[1];
    float mm = fmaxf(s0, s1);
    float e0 = expf(s0 - mm), e1 = expf(s1 - mm);
    float sw = ((gidx < 4) ? e0 : e1) / (e0 + e1);
    float inv = sw / ssum;
    float* ap = g_attn + (size_t)row * NLOG + h * 62 + cbase;
    for (int c = 0; c < len; c++) ap[c] = expf(lp[base + c] - m) * inv;
}

// ---------------------------------------------------------------------------
// Sliding-window weighted sum -> g_x (tf32-rounded for the output GEMM)
// Each thread: 4 consecutive tl x float4 d. One LDS.128 per shared v-row,
// reused across all (tl, c) pairs that touch it.
// ---------------------------------------------------------------------------
__global__ __launch_bounds__(256) void attn_apply_kernel() {
    __shared__ float vs[72][128];
    __shared__ float as_[32][62];

    const int t0 = blockIdx.x * 32;
    const int by = blockIdx.y;       // 0..7 : 128-wide D slice (head = by>>1)
    const int b  = blockIdx.z;
    const int h  = by >> 1;
    const int coff = by * 128;
    const int tid = threadIdx.x;

#pragma unroll
    for (int i = 0; i < 9; i++) {
        int v = tid + i * 256;
        int row = v >> 5;
        int cv = (v & 31) * 4;
        int gt = t0 - 20 + row;
        float4 val = make_float4(0.f, 0.f, 0.f, 0.f);
        if (gt >= 0 && gt < TSEQ)
            val = *(const float4*)(g_qv + (size_t)(b * TSEQ + gt) * NQV + DFEAT + coff + cv);
        *(float4*)(&vs[row][cv]) = val;
    }
    for (int idx = tid; idx < 32 * 62; idx += 256) {
        int tl = idx / 62, c = idx % 62;
        as_[tl][c] = g_attn[(size_t)(b * TSEQ + t0 + tl) * NLOG + h * 62 + c];
    }
    __syncthreads();

    const int d4  = (tid & 31) * 4;
    const int tl0 = (tid >> 5) * 4;

    float4 acc[4];
#pragma unroll
    for (int tl = 0; tl < 4; tl++) acc[tl] = make_float4(0.f, 0.f, 0.f, 0.f);

    // v-rows tl0 .. tl0+43 cover both windows for tl in [tl0, tl0+3]:
    //   scale1 (c1 in [0,41)): vs row = tl + c1        -> rr = c1 + tl - tl0
    //   scale0 (c0 in [0,21)): vs row = tl + 10 + c0   -> rr = c0 + 10 + tl - tl0
#pragma unroll
    for (int rr = 0; rr < 44; rr++) {
        float4 v = *(const float4*)(&vs[tl0 + rr][d4]);
#pragma unroll
        for (int tl = 0; tl < 4; tl++) {
            int c1 = rr - tl;
            if (c1 >= 0 && c1 < C1) {
                float w = as_[tl0 + tl][C0 + c1];
                acc[tl].x += w * v.x; acc[tl].y += w * v.y;
                acc[tl].z += w * v.z; acc[tl].w += w * v.w;
            }
            int c0 = rr - tl - 10;
            if (c0 >= 0 && c0 < C0) {
                float w = as_[tl0 + tl][c0];
                acc[tl].x += w * v.x; acc[tl].y += w * v.y;
                acc[tl].z += w * v.z; acc[tl].w += w * v.w;
            }
        }
    }

#pragma unroll
    for (int tl = 0; tl < 4; tl++) {
        float4 o;
        o.x = rna_tf32(acc[tl].x); o.y = rna_tf32(acc[tl].y);
        o.z = rna_tf32(acc[tl].z); o.w = rna_tf32(acc[tl].w);
        *(float4*)(g_x + (size_t)(b * TSEQ + t0 + tl0 + tl) * DFEAT + coff + d4) = o;
    }
}

// ---------------------------------------------------------------------------
// Launch
// ---------------------------------------------------------------------------
extern "C" void kernel_launch(void* const* d_in, const int* in_sizes, int n_in,
                              void* d_out, int out_size) {
    const float* query    = (const float*)d_in[0];
    // d_in[1]=key, d_in[2]=value: unused by reference
    const float* W_qv     = (const float*)d_in[3];
    const float* W2_0     = (const float*)d_in[4];
    const float* W2_1     = (const float*)d_in[5];
    const float* sweights = (const float*)d_in[6];
    const float* W_out    = (const float*)d_in[7];
    float* out = (float*)d_out;

    cudaFuncSetAttribute(gemm_tc_kernel, cudaFuncAttributeMaxDynamicSharedMemorySize, GEMM_SMEM);

    void *qtf_p = nullptr, *wqvt_p = nullptr, *woutt_p = nullptr, *w2t_p = nullptr;
    void *qv_p = nullptr, *logits_p = nullptr, *x_p = nullptr;
    cudaGetSymbolAddress(&qtf_p, g_qtf);
    cudaGetSymbolAddress(&wqvt_p, g_wqvt);
    cudaGetSymbolAddress(&woutt_p, g_woutt);
    cudaGetSymbolAddress(&w2t_p, g_w2t);
    cudaGetSymbolAddress(&qv_p, g_qv);
    cudaGetSymbolAddress(&logits_p, g_logits);
    cudaGetSymbolAddress(&x_p, g_x);

    // 1) prep
    round_query_kernel<<<(MROWS * DFEAT / 4 + 255) / 256, 256>>>(
        (const float4*)query, (float4*)qtf_p, MROWS * DFEAT / 4);
    transpose_round_kernel<<<dim3(NQV / 32, DFEAT / 32), 256>>>(W_qv, (float*)wqvt_p, DFEAT, NQV);
    transpose_round_kernel<<<dim3(DFEAT / 32, DFEAT / 32), 256>>>(W_out, (float*)woutt_p, DFEAT, DFEAT);
    pack_w2t_kernel<<<NLOGPAD * DFEAT / 256, 256>>>(W2_0, W2_1);

    // 2) qv = query @ W_qv  (relu + tf32-round on q half)
    gemm_tc_kernel<<<dim3(NQV / BN, MROWS / BM), 256, GEMM_SMEM>>>(
        (const float*)qtf_p, DFEAT, (const float*)wqvt_p, DFEAT,
        (float*)qv_p, NQV, DFEAT, DFEAT);

    // 3) logits = relu(q) @ W2
    gemm_tc_kernel<<<dim3(NLOGPAD / BN, MROWS / BM), 256, GEMM_SMEM>>>(
        (const float*)qv_p, NQV, (const float*)w2t_p, DFEAT,
        (float*)logits_p, NLOGPAD, DFEAT, 0);

    // 4) per-group softmax + scale weighting
    softmax_kernel<<<(MROWS * 8 + 255) / 256, 256>>>(sweights);

    // 5) sliding-window weighted sum
    attn_apply_kernel<<<dim3(TSEQ / 32, 8, BATCH), 256>>>();

    // 6) out = g_x @ W_out
    gemm_tc_kernel<<<dim3(DFEAT / BN, MROWS / BM), 256, GEMM_SMEM>>>(
        (const float*)x_p, DFEAT, (const float*)woutt_p, DFEAT,
        out, DFEAT, DFEAT, 0);
}

// round 5
// speedup vs baseline: 3.9386x; 1.1467x over previous
#include <cuda_runtime.h>
#include <cuda_bf16.h>
#include <math.h>
#include <stdint.h>

// ---------------------------------------------------------------------------
// Problem constants
// ---------------------------------------------------------------------------
#define BATCH   4
#define TSEQ    1024
#define DFEAT   1024
#define NQV     2048
#define MROWS   (BATCH * TSEQ)   // 4096
#define C0      21
#define C1      41
#define NLOG    248
#define NLOGPAD 256

// ---------------------------------------------------------------------------
// Scratch (no cudaMalloc allowed)
// ---------------------------------------------------------------------------
__device__ float g_qtf  [(size_t)MROWS * DFEAT];    // tf32-rounded query
__device__ float g_wqvt [(size_t)NQV * DFEAT];      // W_qv^T  [2048,1024], tf32-rounded
__device__ float g_woutt[(size_t)DFEAT * DFEAT];    // W_out^T [1024,1024], tf32-rounded
__device__ float g_w2t  [(size_t)NLOGPAD * DFEAT];  // packed W2^T [256,1024], tf32-rounded
__device__ float g_qv   [(size_t)MROWS * NQV];      // cols<1024: relu(q) tf32-rounded; >=1024: v
__device__ float g_logits[(size_t)MROWS * NLOGPAD];
__device__ float g_attn [(size_t)MROWS * NLOG];     // [bt][h][62], pre-scaled by sw
__device__ float g_x    [(size_t)MROWS * DFEAT];    // mixed output (tf32-rounded)

// ---------------------------------------------------------------------------
// Helpers
// ---------------------------------------------------------------------------
__device__ __forceinline__ uint32_t smem_u32(const void* p) {
    uint32_t a;
    asm("{ .reg .u64 t; cvta.to.shared.u64 t, %1; cvt.u32.u64 %0, t; }" : "=r"(a) : "l"(p));
    return a;
}
__device__ __forceinline__ float rna_tf32(float x) {
    uint32_t u; asm("cvt.rna.tf32.f32 %0, %1;" : "=r"(u) : "f"(x));
    return __uint_as_float(u);
}
__device__ __forceinline__ void cp_async16(uint32_t dst, const void* src) {
    asm volatile("cp.async.cg.shared.global [%0], [%1], 16;" :: "r"(dst), "l"(src));
}
__device__ __forceinline__ void cp_commit() {
    asm volatile("cp.async.commit_group;" ::: "memory");
}
__device__ __forceinline__ void ldsm4(uint32_t* r, uint32_t addr) {
    asm volatile("ldmatrix.sync.aligned.m8n8.x4.shared.b16 {%0,%1,%2,%3}, [%4];"
        : "=r"(r[0]), "=r"(r[1]), "=r"(r[2]), "=r"(r[3]) : "r"(addr));
}
__device__ __forceinline__ void mma_tf32(float* c, const uint32_t* a, const uint32_t* b) {
    asm volatile("mma.sync.aligned.m16n8k8.row.col.f32.tf32.tf32.f32 "
        "{%0,%1,%2,%3}, {%4,%5,%6,%7}, {%8,%9}, {%0,%1,%2,%3};"
        : "+f"(c[0]), "+f"(c[1]), "+f"(c[2]), "+f"(c[3])
        : "r"(a[0]), "r"(a[1]), "r"(a[2]), "r"(a[3]), "r"(b[0]), "r"(b[1]));
}

// ---------------------------------------------------------------------------
// Prep kernels
// ---------------------------------------------------------------------------
__global__ void round_query_kernel(const float4* __restrict__ in, float4* __restrict__ out, int n4) {
    int i = blockIdx.x * 256 + threadIdx.x;
    if (i < n4) {
        float4 v = in[i];
        v.x = rna_tf32(v.x); v.y = rna_tf32(v.y); v.z = rna_tf32(v.z); v.w = rna_tf32(v.w);
        out[i] = v;
    }
}

// in [K,N] row-major -> out [N,K] row-major, tf32-rounded
__global__ void transpose_round_kernel(const float* __restrict__ in, float* __restrict__ out,
                                       int K, int N) {
    __shared__ float t[32][33];
    int n0 = blockIdx.x * 32, k0 = blockIdx.y * 32;
    int tx = threadIdx.x & 31, ty = threadIdx.x >> 5;
#pragma unroll
    for (int i = 0; i < 4; i++)
        t[ty + i * 8][tx] = in[(size_t)(k0 + ty + i * 8) * N + n0 + tx];
    __syncthreads();
#pragma unroll
    for (int i = 0; i < 4; i++)
        out[(size_t)(n0 + ty + i * 8) * K + k0 + tx] = rna_tf32(t[tx][ty + i * 8]);
}

// pack W2_0 [1024,84], W2_1 [1024,164] -> g_w2t [256,1024] transposed, padded, rounded
__global__ void pack_w2t_kernel(const float* __restrict__ w20, const float* __restrict__ w21) {
    int idx = blockIdx.x * 256 + threadIdx.x;    // 0 .. 256*1024-1
    int n = idx >> 10, k = idx & 1023;
    float v = 0.f;
    if (n < 84)       v = w20[k * 84 + n];
    else if (n < 248) v = w21[k * 164 + (n - 84)];
    g_w2t[idx] = rna_tf32(v);
}

// ---------------------------------------------------------------------------
// tf32 mma.sync GEMM: C[M,N] = A[M,K] @ Bt[N,K]^T
// Template: TBM (block m-tile), TWM (warp m-tile). N tile fixed 128,
// warp n-tile fixed 32, 8 warps as (TBM/TWM) x (128/32) grid. BK=32,
// 3-stage cp.async, XOR-swizzled smem, ldmatrix.x4 fragments.
// __launch_bounds__(256, 2) caps regs at 128 -> 2 CTAs/SM (occupancy!).
// Epilogue: cols < relu_cols get relu + tf32-round.
// ---------------------------------------------------------------------------
#define BK 32
#define NSTAGE 3

template <int TBM, int TWM>
__global__ __launch_bounds__(256, 2)
void gemm_tc_kernel(const float* __restrict__ A, int lda,
                    const float* __restrict__ Bt, int ldb,
                    float* __restrict__ C, int ldc,
                    int K, int relu_cols) {
    constexpr int STB = (TBM + 128) * BK * 4;   // stage bytes
    constexpr int MT  = TWM / 16;               // m fragments per warp
    constexpr int WM_CNT = TBM / TWM;           // warps along m (=2)

    extern __shared__ char smem[];
    const uint32_t sb = smem_u32(smem);
    const int tid = threadIdx.x;
    const int lane = tid & 31, warp = tid >> 5;
    const int wm = (warp & (WM_CNT - 1)) * TWM;
    const int wn = (warp / WM_CNT) * 32;
    const int mBase = blockIdx.y * TBM;
    const int nBase = blockIdx.x * 128;
    const int lrow = lane & 7, mat = lane >> 3;

    const float* Abase = A + (size_t)mBase * lda;
    const float* Bbase = Bt + (size_t)nBase * ldb;
    const int NIT = K / BK;

    float acc[MT][4][4];
#pragma unroll
    for (int i = 0; i < MT; i++)
#pragma unroll
        for (int j = 0; j < 4; j++)
#pragma unroll
            for (int l = 0; l < 4; l++) acc[i][j][l] = 0.f;

    // tile loader (lambda-ish via macro-free inline)
    auto load_tile = [&](uint32_t stageBase, const float* Ag, const float* Bg) {
#pragma unroll
        for (int i = 0; i < TBM / 32; i++) {
            int cid = tid + i * 256;
            int r = cid >> 3, ch = cid & 7;
            uint32_t dst = stageBase + r * 128 + ((ch ^ (r & 7)) << 4);
            cp_async16(dst, Ag + (size_t)r * lda + ch * 4);
        }
        uint32_t bBase = stageBase + TBM * BK * 4;
#pragma unroll
        for (int i = 0; i < 4; i++) {
            int cid = tid + i * 256;
            int r = cid >> 3, ch = cid & 7;
            uint32_t dst = bBase + r * 128 + ((ch ^ (r & 7)) << 4);
            cp_async16(dst, Bg + (size_t)r * ldb + ch * 4);
        }
    };

    load_tile(sb, Abase, Bbase); cp_commit();
    load_tile(sb + STB, Abase + BK, Bbase + BK); cp_commit();

    int arow[MT], brow[2];
#pragma unroll
    for (int mt = 0; mt < MT; mt++) arow[mt] = wm + mt * 16 + ((mat & 1) << 3) + lrow;
#pragma unroll
    for (int nb = 0; nb < 2; nb++) brow[nb] = wn + nb * 16 + ((mat >> 1) << 3) + lrow;
    const int achunk = (mat >> 1);   // + 2*kk
    const int bchunk = (mat & 1);    // + 2*kk

    for (int it = 0; it < NIT; it++) {
        int s = it - (it / 3) * 3;
        asm volatile("cp.async.wait_group 1;" ::: "memory");
        __syncthreads();

        uint32_t aTile = sb + s * STB;
        uint32_t bTile = aTile + TBM * BK * 4;

#pragma unroll
        for (int kk = 0; kk < 4; kk++) {
            uint32_t af[MT][4], bf[4][2];
#pragma unroll
            for (int mt = 0; mt < MT; mt++) {
                int ch = 2 * kk + achunk;
                uint32_t addr = aTile + arow[mt] * 128 + ((ch ^ (arow[mt] & 7)) << 4);
                ldsm4(af[mt], addr);
            }
#pragma unroll
            for (int nb = 0; nb < 2; nb++) {
                int ch = 2 * kk + bchunk;
                uint32_t addr = bTile + brow[nb] * 128 + ((ch ^ (brow[nb] & 7)) << 4);
                uint32_t r[4];
                ldsm4(r, addr);
                bf[nb * 2][0] = r[0]; bf[nb * 2][1] = r[1];
                bf[nb * 2 + 1][0] = r[2]; bf[nb * 2 + 1][1] = r[3];
            }
#pragma unroll
            for (int mt = 0; mt < MT; mt++)
#pragma unroll
                for (int nt = 0; nt < 4; nt++)
                    mma_tf32(acc[mt][nt], af[mt], bf[nt]);
        }

        if (it + 2 < NIT) {
            int sw = (it + 2) - ((it + 2) / 3) * 3;
            load_tile(sb + sw * STB, Abase + (it + 2) * BK, Bbase + (it + 2) * BK);
        }
        cp_commit();   // keep group count uniform
    }

    // epilogue
    const int g = lane >> 2, tig = lane & 3;
#pragma unroll
    for (int mt = 0; mt < MT; mt++) {
#pragma unroll
        for (int nt = 0; nt < 4; nt++) {
            int row = mBase + wm + mt * 16 + g;
            int col = nBase + wn + nt * 8 + tig * 2;
            float2 v0 = make_float2(acc[mt][nt][0], acc[mt][nt][1]);
            float2 v1 = make_float2(acc[mt][nt][2], acc[mt][nt][3]);
            if (col < relu_cols) {
                v0.x = rna_tf32(fmaxf(v0.x, 0.f)); v0.y = rna_tf32(fmaxf(v0.y, 0.f));
                v1.x = rna_tf32(fmaxf(v1.x, 0.f)); v1.y = rna_tf32(fmaxf(v1.y, 0.f));
            }
            *(float2*)(C + (size_t)row * ldc + col) = v0;
            *(float2*)(C + (size_t)(row + 8) * ldc + col) = v1;
        }
    }
}

// ---------------------------------------------------------------------------
// Softmax over logits groups -> g_attn (pre-scaled by softmax(scale_weights))
// ---------------------------------------------------------------------------
__global__ void softmax_kernel(const float* __restrict__ sweights) {
    int idx = blockIdx.x * 256 + threadIdx.x;
    if (idx >= MROWS * 8) return;
    int row = idx >> 3, gidx = idx & 7;
    const float* lp = g_logits + (size_t)row * NLOGPAD;
    int base, len, h, cbase;
    if (gidx < 4) { base = gidx * 21;            len = 21; h = gidx;     cbase = 0; }
    else          { base = 84 + (gidx - 4) * 41; len = 41; h = gidx - 4; cbase = 21; }
    float m = -1e30f;
    for (int c = 0; c < len; c++) m = fmaxf(m, lp[base + c]);
    float ssum = 0.f;
    for (int c = 0; c < len; c++) ssum += expf(lp[base + c] - m);
    float s0 = sweights[0], s1 = sweights[1];
    float mm = fmaxf(s0, s1);
    float e0 = expf(s0 - mm), e1 = expf(s1 - mm);
    float sw = ((gidx < 4) ? e0 : e1) / (e0 + e1);
    float inv = sw / ssum;
    float* ap = g_attn + (size_t)row * NLOG + h * 62 + cbase;
    for (int c = 0; c < len; c++) ap[c] = expf(lp[base + c] - m) * inv;
}

// ---------------------------------------------------------------------------
// Sliding-window weighted sum -> g_x (tf32-rounded for the output GEMM)
// Each thread: 4 consecutive tl x float4 d; one LDS.128 per shared v-row.
// ---------------------------------------------------------------------------
__global__ __launch_bounds__(256) void attn_apply_kernel() {
    __shared__ float vs[72][128];
    __shared__ float as_[32][62];

    const int t0 = blockIdx.x * 32;
    const int by = blockIdx.y;       // 0..7 : 128-wide D slice (head = by>>1)
    const int b  = blockIdx.z;
    const int h  = by >> 1;
    const int coff = by * 128;
    const int tid = threadIdx.x;

#pragma unroll
    for (int i = 0; i < 9; i++) {
        int v = tid + i * 256;
        int row = v >> 5;
        int cv = (v & 31) * 4;
        int gt = t0 - 20 + row;
        float4 val = make_float4(0.f, 0.f, 0.f, 0.f);
        if (gt >= 0 && gt < TSEQ)
            val = *(const float4*)(g_qv + (size_t)(b * TSEQ + gt) * NQV + DFEAT + coff + cv);
        *(float4*)(&vs[row][cv]) = val;
    }
    for (int idx = tid; idx < 32 * 62; idx += 256) {
        int tl = idx / 62, c = idx % 62;
        as_[tl][c] = g_attn[(size_t)(b * TSEQ + t0 + tl) * NLOG + h * 62 + c];
    }
    __syncthreads();

    const int d4  = (tid & 31) * 4;
    const int tl0 = (tid >> 5) * 4;

    float4 acc[4];
#pragma unroll
    for (int tl = 0; tl < 4; tl++) acc[tl] = make_float4(0.f, 0.f, 0.f, 0.f);

#pragma unroll
    for (int rr = 0; rr < 44; rr++) {
        float4 v = *(const float4*)(&vs[tl0 + rr][d4]);
#pragma unroll
        for (int tl = 0; tl < 4; tl++) {
            int c1 = rr - tl;
            if (c1 >= 0 && c1 < C1) {
                float w = as_[tl0 + tl][C0 + c1];
                acc[tl].x += w * v.x; acc[tl].y += w * v.y;
                acc[tl].z += w * v.z; acc[tl].w += w * v.w;
            }
            int c0 = rr - tl - 10;
            if (c0 >= 0 && c0 < C0) {
                float w = as_[tl0 + tl][c0];
                acc[tl].x += w * v.x; acc[tl].y += w * v.y;
                acc[tl].z += w * v.z; acc[tl].w += w * v.w;
            }
        }
    }

#pragma unroll
    for (int tl = 0; tl < 4; tl++) {
        float4 o;
        o.x = rna_tf32(acc[tl].x); o.y = rna_tf32(acc[tl].y);
        o.z = rna_tf32(acc[tl].z); o.w = rna_tf32(acc[tl].w);
        *(float4*)(g_x + (size_t)(b * TSEQ + t0 + tl0 + tl) * DFEAT + coff + d4) = o;
    }
}

// ---------------------------------------------------------------------------
// Launch
// ---------------------------------------------------------------------------
extern "C" void kernel_launch(void* const* d_in, const int* in_sizes, int n_in,
                              void* d_out, int out_size) {
    const float* query    = (const float*)d_in[0];
    // d_in[1]=key, d_in[2]=value: unused by reference
    const float* W_qv     = (const float*)d_in[3];
    const float* W2_0     = (const float*)d_in[4];
    const float* W2_1     = (const float*)d_in[5];
    const float* sweights = (const float*)d_in[6];
    const float* W_out    = (const float*)d_in[7];
    float* out = (float*)d_out;

    constexpr int SMEM_128 = NSTAGE * (128 + 128) * BK * 4;   // 98304
    constexpr int SMEM_64  = NSTAGE * (64 + 128) * BK * 4;    // 73728
    cudaFuncSetAttribute(gemm_tc_kernel<128, 64>,
                         cudaFuncAttributeMaxDynamicSharedMemorySize, SMEM_128);
    cudaFuncSetAttribute(gemm_tc_kernel<64, 32>,
                         cudaFuncAttributeMaxDynamicSharedMemorySize, SMEM_64);

    void *qtf_p = nullptr, *wqvt_p = nullptr, *woutt_p = nullptr, *w2t_p = nullptr;
    void *qv_p = nullptr, *logits_p = nullptr, *x_p = nullptr;
    cudaGetSymbolAddress(&qtf_p, g_qtf);
    cudaGetSymbolAddress(&wqvt_p, g_wqvt);
    cudaGetSymbolAddress(&woutt_p, g_woutt);
    cudaGetSymbolAddress(&w2t_p, g_w2t);
    cudaGetSymbolAddress(&qv_p, g_qv);
    cudaGetSymbolAddress(&logits_p, g_logits);
    cudaGetSymbolAddress(&x_p, g_x);

    // 1) prep
    round_query_kernel<<<(MROWS * DFEAT / 4 + 255) / 256, 256>>>(
        (const float4*)query, (float4*)qtf_p, MROWS * DFEAT / 4);
    transpose_round_kernel<<<dim3(NQV / 32, DFEAT / 32), 256>>>(W_qv, (float*)wqvt_p, DFEAT, NQV);
    transpose_round_kernel<<<dim3(DFEAT / 32, DFEAT / 32), 256>>>(W_out, (float*)woutt_p, DFEAT, DFEAT);
    pack_w2t_kernel<<<NLOGPAD * DFEAT / 256, 256>>>(W2_0, W2_1);

    // 2) qv = query @ W_qv  (relu + tf32-round on q half)
    gemm_tc_kernel<128, 64><<<dim3(NQV / 128, MROWS / 128), 256, SMEM_128>>>(
        (const float*)qtf_p, DFEAT, (const float*)wqvt_p, DFEAT,
        (float*)qv_p, NQV, DFEAT, DFEAT);

    // 3) logits = relu(q) @ W2  (small-tile: 128 CTAs instead of 32)
    gemm_tc_kernel<64, 32><<<dim3(NLOGPAD / 128, MROWS / 64), 256, SMEM_64>>>(
        (const float*)qv_p, NQV, (const float*)w2t_p, DFEAT,
        (float*)logits_p, NLOGPAD, DFEAT, 0);

    // 4) per-group softmax + scale weighting
    softmax_kernel<<<(MROWS * 8 + 255) / 256, 256>>>(sweights);

    // 5) sliding-window weighted sum
    attn_apply_kernel<<<dim3(TSEQ / 32, 8, BATCH), 256>>>();

    // 6) out = g_x @ W_out
    gemm_tc_kernel<128, 64><<<dim3(DFEAT / 128, MROWS / 128), 256, SMEM_128>>>(
        (const float*)x_p, DFEAT, (const float*)woutt_p, DFEAT,
        out, DFEAT, DFEAT, 0);
}

// round 6
// speedup vs baseline: 5.9603x; 1.5133x over previous
#include <cuda_runtime.h>
#include <cuda_fp16.h>
#include <math.h>
#include <stdint.h>

// ---------------------------------------------------------------------------
// Problem constants
// ---------------------------------------------------------------------------
#define BATCH   4
#define TSEQ    1024
#define DFEAT   1024
#define NQV     2048
#define MROWS   (BATCH * TSEQ)   // 4096
#define C0      21
#define C1      41
#define NLOG    248
#define NLOGPAD 256

// ---------------------------------------------------------------------------
// Scratch (no cudaMalloc allowed)
// ---------------------------------------------------------------------------
__device__ __half g_qh    [(size_t)MROWS * DFEAT];    // query, fp16
__device__ __half g_wqvth [(size_t)NQV * DFEAT];      // W_qv^T  [2048,1024] fp16
__device__ __half g_woutth[(size_t)DFEAT * DFEAT];    // W_out^T [1024,1024] fp16
__device__ __half g_w2th  [(size_t)NLOGPAD * DFEAT];  // packed W2^T [256,1024] fp16
__device__ __half g_qrelu [(size_t)MROWS * DFEAT];    // relu(q) fp16
__device__ float  g_v     [(size_t)MROWS * DFEAT];    // v fp32
__device__ float  g_logits[(size_t)MROWS * NLOGPAD];
__device__ float  g_attn  [(size_t)MROWS * NLOG];     // [bt][h][62], pre-scaled by sw
__device__ __half g_xh    [(size_t)MROWS * DFEAT];    // mixed output fp16

// ---------------------------------------------------------------------------
// Helpers
// ---------------------------------------------------------------------------
__device__ __forceinline__ uint32_t smem_u32(const void* p) {
    uint32_t a;
    asm("{ .reg .u64 t; cvta.to.shared.u64 t, %1; cvt.u32.u64 %0, t; }" : "=r"(a) : "l"(p));
    return a;
}
__device__ __forceinline__ void cp_async16(uint32_t dst, const void* src) {
    asm volatile("cp.async.cg.shared.global [%0], [%1], 16;" :: "r"(dst), "l"(src));
}
__device__ __forceinline__ void cp_commit() {
    asm volatile("cp.async.commit_group;" ::: "memory");
}
__device__ __forceinline__ void ldsm4(uint32_t* r, uint32_t addr) {
    asm volatile("ldmatrix.sync.aligned.m8n8.x4.shared.b16 {%0,%1,%2,%3}, [%4];"
        : "=r"(r[0]), "=r"(r[1]), "=r"(r[2]), "=r"(r[3]) : "r"(addr));
}
__device__ __forceinline__ void mma_f16(float* c, const uint32_t* a, const uint32_t* b) {
    asm volatile("mma.sync.aligned.m16n8k16.row.col.f32.f16.f16.f32 "
        "{%0,%1,%2,%3}, {%4,%5,%6,%7}, {%8,%9}, {%0,%1,%2,%3};"
        : "+f"(c[0]), "+f"(c[1]), "+f"(c[2]), "+f"(c[3])
        : "r"(a[0]), "r"(a[1]), "r"(a[2]), "r"(a[3]), "r"(b[0]), "r"(b[1]));
}

// ---------------------------------------------------------------------------
// Prep kernels (fp32 -> fp16)
// ---------------------------------------------------------------------------
__global__ void cvt_query_kernel(const float4* __restrict__ in, __half* __restrict__ out, int n4) {
    int i = blockIdx.x * 256 + threadIdx.x;
    if (i < n4) {
        float4 v = in[i];
        __half2 h0 = __floats2half2_rn(v.x, v.y);
        __half2 h1 = __floats2half2_rn(v.z, v.w);
        *(uint2*)(out + (size_t)i * 4) = make_uint2(
            *(uint32_t*)&h0, *(uint32_t*)&h1);
    }
}

// in [K,N] row-major fp32 -> out [N,K] row-major fp16
__global__ void transpose_h_kernel(const float* __restrict__ in, __half* __restrict__ out,
                                   int K, int N) {
    __shared__ float t[32][33];
    int n0 = blockIdx.x * 32, k0 = blockIdx.y * 32;
    int tx = threadIdx.x & 31, ty = threadIdx.x >> 5;
#pragma unroll
    for (int i = 0; i < 4; i++)
        t[ty + i * 8][tx] = in[(size_t)(k0 + ty + i * 8) * N + n0 + tx];
    __syncthreads();
#pragma unroll
    for (int i = 0; i < 4; i++)
        out[(size_t)(n0 + ty + i * 8) * K + k0 + tx] = __float2half_rn(t[tx][ty + i * 8]);
}

// pack W2_0 [1024,84], W2_1 [1024,164] -> g_w2th [256,1024] transposed, padded, fp16
__global__ void pack_w2th_kernel(const float* __restrict__ w20, const float* __restrict__ w21) {
    int idx = blockIdx.x * 256 + threadIdx.x;    // 0 .. 256*1024-1
    int n = idx >> 10, k = idx & 1023;
    float v = 0.f;
    if (n < 84)       v = w20[k * 84 + n];
    else if (n < 248) v = w21[k * 164 + (n - 84)];
    g_w2th[idx] = __float2half_rn(v);
}

// ---------------------------------------------------------------------------
// fp16 mma.sync GEMM: C[M,N] = A[M,K] @ Bt[N,K]^T, fp32 accumulate.
// Template: TBM (block m-tile), TWM (warp m-tile). N tile 128,
// warp n-tile 32, 8 warps. BK=64 (128B rows -> SW128 swizzle, conflict-free
// ldmatrix). 3-stage cp.async. __launch_bounds__(256,2) -> 2 CTAs/SM.
// mode 0: plain fp32 store to Cq.
// mode 1 (qv split): global col < DFEAT -> relu -> fp16 into (half*)Cq;
//                    col >= DFEAT -> fp32 into (float*)Cv, col-DFEAT.
// ---------------------------------------------------------------------------
#define BK 64
#define NSTAGE 3

template <int TBM, int TWM, int MODE>
__global__ __launch_bounds__(256, 2)
void hgemm_kernel(const __half* __restrict__ A, int lda,
                  const __half* __restrict__ Bt, int ldb,
                  void* __restrict__ Cq, void* __restrict__ Cv,
                  int ldc, int K) {
    constexpr int STB = (TBM + 128) * BK * 2;   // stage bytes
    constexpr int MT  = TWM / 16;
    constexpr int WM_CNT = TBM / TWM;

    extern __shared__ char smem[];
    const uint32_t sb = smem_u32(smem);
    const int tid = threadIdx.x;
    const int lane = tid & 31, warp = tid >> 5;
    const int wm = (warp & (WM_CNT - 1)) * TWM;
    const int wn = (warp / WM_CNT) * 32;
    const int mBase = blockIdx.y * TBM;
    const int nBase = blockIdx.x * 128;
    const int lrow = lane & 7, mat = lane >> 3;

    const __half* Abase = A + (size_t)mBase * lda;
    const __half* Bbase = Bt + (size_t)nBase * ldb;
    const int NIT = K / BK;

    float acc[MT][4][4];
#pragma unroll
    for (int i = 0; i < MT; i++)
#pragma unroll
        for (int j = 0; j < 4; j++)
#pragma unroll
            for (int l = 0; l < 4; l++) acc[i][j][l] = 0.f;

    // tile loader: rows have 64 halves = 128 bytes = 8 x 16B chunks
    auto load_tile = [&](uint32_t stageBase, const __half* Ag, const __half* Bg) {
#pragma unroll
        for (int i = 0; i < TBM / 32; i++) {
            int cid = tid + i * 256;
            int r = cid >> 3, ch = cid & 7;
            uint32_t dst = stageBase + r * 128 + ((ch ^ (r & 7)) << 4);
            cp_async16(dst, Ag + (size_t)r * lda + ch * 8);
        }
        uint32_t bBase = stageBase + TBM * BK * 2;
#pragma unroll
        for (int i = 0; i < 4; i++) {
            int cid = tid + i * 256;
            int r = cid >> 3, ch = cid & 7;
            uint32_t dst = bBase + r * 128 + ((ch ^ (r & 7)) << 4);
            cp_async16(dst, Bg + (size_t)r * ldb + ch * 8);
        }
    };

    load_tile(sb, Abase, Bbase); cp_commit();
    load_tile(sb + STB, Abase + BK, Bbase + BK); cp_commit();

    // ldmatrix addressing:
    // A frag (m16k16): mat bit0 -> m+8, bit1 -> k-chunk+1
    // B frag (two n8 tiles): mat bit1 -> n+8, bit0 -> k-chunk+1
    int arow[MT], brow[2];
#pragma unroll
    for (int mt = 0; mt < MT; mt++) arow[mt] = wm + mt * 16 + ((mat & 1) << 3) + lrow;
#pragma unroll
    for (int nb = 0; nb < 2; nb++) brow[nb] = wn + nb * 16 + ((mat >> 1) << 3) + lrow;
    const int achunk = (mat >> 1);   // + 2*kk
    const int bchunk = (mat & 1);    // + 2*kk

    for (int it = 0; it < NIT; it++) {
        int s = it - (it / 3) * 3;
        asm volatile("cp.async.wait_group 1;" ::: "memory");
        __syncthreads();

        uint32_t aTile = sb + s * STB;
        uint32_t bTile = aTile + TBM * BK * 2;

#pragma unroll
        for (int kk = 0; kk < 4; kk++) {         // 4 x k16 per BK=64
            uint32_t af[MT][4], bf[4][2];
#pragma unroll
            for (int mt = 0; mt < MT; mt++) {
                int ch = 2 * kk + achunk;
                uint32_t addr = aTile + arow[mt] * 128 + ((ch ^ (arow[mt] & 7)) << 4);
                ldsm4(af[mt], addr);
            }
#pragma unroll
            for (int nb = 0; nb < 2; nb++) {
                int ch = 2 * kk + bchunk;
                uint32_t addr = bTile + brow[nb] * 128 + ((ch ^ (brow[nb] & 7)) << 4);
                uint32_t r[4];
                ldsm4(r, addr);
                bf[nb * 2][0] = r[0]; bf[nb * 2][1] = r[1];
                bf[nb * 2 + 1][0] = r[2]; bf[nb * 2 + 1][1] = r[3];
            }
#pragma unroll
            for (int mt = 0; mt < MT; mt++)
#pragma unroll
                for (int nt = 0; nt < 4; nt++)
                    mma_f16(acc[mt][nt], af[mt], bf[nt]);
        }

        if (it + 2 < NIT) {
            int sw = (it + 2) - ((it + 2) / 3) * 3;
            load_tile(sb + sw * STB, Abase + (it + 2) * BK, Bbase + (it + 2) * BK);
        }
        cp_commit();   // keep group count uniform
    }

    // epilogue
    const int g = lane >> 2, tig = lane & 3;
#pragma unroll
    for (int mt = 0; mt < MT; mt++) {
#pragma unroll
        for (int nt = 0; nt < 4; nt++) {
            int row = mBase + wm + mt * 16 + g;
            int col = nBase + wn + nt * 8 + tig * 2;
            if (MODE == 0) {
                float* C = (float*)Cq;
                *(float2*)(C + (size_t)row * ldc + col) =
                    make_float2(acc[mt][nt][0], acc[mt][nt][1]);
                *(float2*)(C + (size_t)(row + 8) * ldc + col) =
                    make_float2(acc[mt][nt][2], acc[mt][nt][3]);
            } else {
                if (col < DFEAT) {
                    __half* Q = (__half*)Cq;
                    __half2 h0 = __floats2half2_rn(fmaxf(acc[mt][nt][0], 0.f),
                                                   fmaxf(acc[mt][nt][1], 0.f));
                    __half2 h1 = __floats2half2_rn(fmaxf(acc[mt][nt][2], 0.f),
                                                   fmaxf(acc[mt][nt][3], 0.f));
                    *(__half2*)(Q + (size_t)row * DFEAT + col) = h0;
                    *(__half2*)(Q + (size_t)(row + 8) * DFEAT + col) = h1;
                } else {
                    float* V = (float*)Cv;
                    int vc = col - DFEAT;
                    *(float2*)(V + (size_t)row * DFEAT + vc) =
                        make_float2(acc[mt][nt][0], acc[mt][nt][1]);
                    *(float2*)(V + (size_t)(row + 8) * DFEAT + vc) =
                        make_float2(acc[mt][nt][2], acc[mt][nt][3]);
                }
            }
        }
    }
}

// ---------------------------------------------------------------------------
// Softmax over logits groups -> g_attn (pre-scaled by softmax(scale_weights))
// ---------------------------------------------------------------------------
__global__ void softmax_kernel(const float* __restrict__ sweights) {
    int idx = blockIdx.x * 256 + threadIdx.x;
    if (idx >= MROWS * 8) return;
    int row = idx >> 3, gidx = idx & 7;
    const float* lp = g_logits + (size_t)row * NLOGPAD;
    int base, len, h, cbase;
    if (gidx < 4) { base = gidx * 21;            len = 21; h = gidx;     cbase = 0; }
    else          { base = 84 + (gidx - 4) * 41; len = 41; h = gidx - 4; cbase = 21; }
    float m = -1e30f;
    for (int c = 0; c < len; c++) m = fmaxf(m, lp[base + c]);
    float ssum = 0.f;
    for (int c = 0; c < len; c++) ssum += expf(lp[base + c] - m);
    float s0 = sweights[0], s1 = sweights[1];
    float mm = fmaxf(s0, s1);
    float e0 = expf(s0 - mm), e1 = expf(s1 - mm);
    float sw = ((gidx < 4) ? e0 : e1) / (e0 + e1);
    float inv = sw / ssum;
    float* ap = g_attn + (size_t)row * NLOG + h * 62 + cbase;
    for (int c = 0; c < len; c++) ap[c] = expf(lp[base + c] - m) * inv;
}

// ---------------------------------------------------------------------------
// Sliding-window weighted sum -> g_xh (fp16 for the output GEMM)
// Each thread: 4 consecutive tl x float4 d; one LDS.128 per shared v-row.
// ---------------------------------------------------------------------------
__global__ __launch_bounds__(256) void attn_apply_kernel() {
    __shared__ float vs[72][128];
    __shared__ float as_[32][62];

    const int t0 = blockIdx.x * 32;
    const int by = blockIdx.y;       // 0..7 : 128-wide D slice (head = by>>1)
    const int b  = blockIdx.z;
    const int h  = by >> 1;
    const int coff = by * 128;
    const int tid = threadIdx.x;

#pragma unroll
    for (int i = 0; i < 9; i++) {
        int v = tid + i * 256;
        int row = v >> 5;
        int cv = (v & 31) * 4;
        int gt = t0 - 20 + row;
        float4 val = make_float4(0.f, 0.f, 0.f, 0.f);
        if (gt >= 0 && gt < TSEQ)
            val = *(const float4*)(g_v + (size_t)(b * TSEQ + gt) * DFEAT + coff + cv);
        *(float4*)(&vs[row][cv]) = val;
    }
    for (int idx = tid; idx < 32 * 62; idx += 256) {
        int tl = idx / 62, c = idx % 62;
        as_[tl][c] = g_attn[(size_t)(b * TSEQ + t0 + tl) * NLOG + h * 62 + c];
    }
    __syncthreads();

    const int d4  = (tid & 31) * 4;
    const int tl0 = (tid >> 5) * 4;

    float4 acc[4];
#pragma unroll
    for (int tl = 0; tl < 4; tl++) acc[tl] = make_float4(0.f, 0.f, 0.f, 0.f);

#pragma unroll
    for (int rr = 0; rr < 44; rr++) {
        float4 v = *(const float4*)(&vs[tl0 + rr][d4]);
#pragma unroll
        for (int tl = 0; tl < 4; tl++) {
            int c1 = rr - tl;
            if (c1 >= 0 && c1 < C1) {
                float w = as_[tl0 + tl][C0 + c1];
                acc[tl].x += w * v.x; acc[tl].y += w * v.y;
                acc[tl].z += w * v.z; acc[tl].w += w * v.w;
            }
            int c0 = rr - tl - 10;
            if (c0 >= 0 && c0 < C0) {
                float w = as_[tl0 + tl][c0];
                acc[tl].x += w * v.x; acc[tl].y += w * v.y;
                acc[tl].z += w * v.z; acc[tl].w += w * v.w;
            }
        }
    }

#pragma unroll
    for (int tl = 0; tl < 4; tl++) {
        __half2 h0 = __floats2half2_rn(acc[tl].x, acc[tl].y);
        __half2 h1 = __floats2half2_rn(acc[tl].z, acc[tl].w);
        *(uint2*)(g_xh + (size_t)(b * TSEQ + t0 + tl0 + tl) * DFEAT + coff + d4) =
            make_uint2(*(uint32_t*)&h0, *(uint32_t*)&h1);
    }
}

// ---------------------------------------------------------------------------
// Launch
// ---------------------------------------------------------------------------
extern "C" void kernel_launch(void* const* d_in, const int* in_sizes, int n_in,
                              void* d_out, int out_size) {
    const float* query    = (const float*)d_in[0];
    // d_in[1]=key, d_in[2]=value: unused by reference
    const float* W_qv     = (const float*)d_in[3];
    const float* W2_0     = (const float*)d_in[4];
    const float* W2_1     = (const float*)d_in[5];
    const float* sweights = (const float*)d_in[6];
    const float* W_out    = (const float*)d_in[7];
    float* out = (float*)d_out;

    constexpr int SMEM_128 = NSTAGE * (128 + 128) * BK * 2;   // 98304
    constexpr int SMEM_64  = NSTAGE * (64 + 128) * BK * 2;    // 73728
    cudaFuncSetAttribute(hgemm_kernel<128, 64, 1>,
                         cudaFuncAttributeMaxDynamicSharedMemorySize, SMEM_128);
    cudaFuncSetAttribute(hgemm_kernel<128, 64, 0>,
                         cudaFuncAttributeMaxDynamicSharedMemorySize, SMEM_128);
    cudaFuncSetAttribute(hgemm_kernel<64, 32, 0>,
                         cudaFuncAttributeMaxDynamicSharedMemorySize, SMEM_64);

    void *qh_p = nullptr, *wqvth_p = nullptr, *woutth_p = nullptr;
    void *qrelu_p = nullptr, *v_p = nullptr, *logits_p = nullptr, *xh_p = nullptr, *w2th_p = nullptr;
    cudaGetSymbolAddress(&qh_p, g_qh);
    cudaGetSymbolAddress(&wqvth_p, g_wqvth);
    cudaGetSymbolAddress(&woutth_p, g_woutth);
    cudaGetSymbolAddress(&w2th_p, g_w2th);
    cudaGetSymbolAddress(&qrelu_p, g_qrelu);
    cudaGetSymbolAddress(&v_p, g_v);
    cudaGetSymbolAddress(&logits_p, g_logits);
    cudaGetSymbolAddress(&xh_p, g_xh);

    // 1) prep: fp32 -> fp16 conversions
    cvt_query_kernel<<<(MROWS * DFEAT / 4 + 255) / 256, 256>>>(
        (const float4*)query, (__half*)qh_p, MROWS * DFEAT / 4);
    transpose_h_kernel<<<dim3(NQV / 32, DFEAT / 32), 256>>>(W_qv, (__half*)wqvth_p, DFEAT, NQV);
    transpose_h_kernel<<<dim3(DFEAT / 32, DFEAT / 32), 256>>>(W_out, (__half*)woutth_p, DFEAT, DFEAT);
    pack_w2th_kernel<<<NLOGPAD * DFEAT / 256, 256>>>(W2_0, W2_1);

    // 2) qv = query @ W_qv : q half -> relu -> fp16 g_qrelu; v half -> fp32 g_v
    hgemm_kernel<128, 64, 1><<<dim3(NQV / 128, MROWS / 128), 256, SMEM_128>>>(
        (const __half*)qh_p, DFEAT, (const __half*)wqvth_p, DFEAT,
        qrelu_p, v_p, 0, DFEAT);

    // 3) logits = relu(q) @ W2  (small m-tile: 128 CTAs)
    hgemm_kernel<64, 32, 0><<<dim3(NLOGPAD / 128, MROWS / 64), 256, SMEM_64>>>(
        (const __half*)qrelu_p, DFEAT, (const __half*)w2th_p, DFEAT,
        logits_p, nullptr, NLOGPAD, DFEAT);

    // 4) per-group softmax + scale weighting
    softmax_kernel<<<(MROWS * 8 + 255) / 256, 256>>>(sweights);

    // 5) sliding-window weighted sum -> g_xh (fp16)
    attn_apply_kernel<<<dim3(TSEQ / 32, 8, BATCH), 256>>>();

    // 6) out = x @ W_out
    hgemm_kernel<128, 64, 0><<<dim3(DFEAT / 128, MROWS / 128), 256, SMEM_128>>>(
        (const __half*)xh_p, DFEAT, (const __half*)woutth_p, DFEAT,
        out, nullptr, DFEAT, DFEAT);
}

// round 7
// speedup vs baseline: 6.0393x; 1.0132x over previous
#include <cuda_runtime.h>
#include <cuda_fp16.h>
#include <math.h>
#include <stdint.h>

// ---------------------------------------------------------------------------
// Problem constants
// ---------------------------------------------------------------------------
#define BATCH   4
#define TSEQ    1024
#define DFEAT   1024
#define NQV     2048
#define MROWS   (BATCH * TSEQ)   // 4096
#define C0      21
#define C1      41
#define NLOGPAD 256
#define WSTRIDE 176              // g_attn row stride: 4 heads * 44

// ---------------------------------------------------------------------------
// Scratch (no cudaMalloc allowed)
// ---------------------------------------------------------------------------
__device__ __half g_qh    [(size_t)MROWS * DFEAT];    // query fp16
__device__ __half g_wqvh  [(size_t)DFEAT * NQV];      // W_qv  [1024,2048] fp16 (natural)
__device__ __half g_wouth [(size_t)DFEAT * DFEAT];    // W_out [1024,1024] fp16 (natural)
__device__ __half g_w2h   [(size_t)DFEAT * NLOGPAD];  // packed W2 [1024,256] fp16 (natural)
__device__ __half g_qrelu [(size_t)MROWS * DFEAT];    // relu(q) fp16
__device__ float  g_v     [(size_t)MROWS * DFEAT];    // v fp32
__device__ float  g_logits[(size_t)MROWS * NLOGPAD];
__device__ float  g_attn  [(size_t)MROWS * WSTRIDE];  // fused 41-tap weights [bt][h][44]
__device__ __half g_xh    [(size_t)MROWS * DFEAT];    // mixed output fp16

// ---------------------------------------------------------------------------
// Helpers
// ---------------------------------------------------------------------------
__device__ __forceinline__ uint32_t smem_u32(const void* p) {
    uint32_t a;
    asm("{ .reg .u64 t; cvta.to.shared.u64 t, %1; cvt.u32.u64 %0, t; }" : "=r"(a) : "l"(p));
    return a;
}
__device__ __forceinline__ void cp_async16(uint32_t dst, const void* src) {
    asm volatile("cp.async.cg.shared.global [%0], [%1], 16;" :: "r"(dst), "l"(src));
}
__device__ __forceinline__ void cp_commit() {
    asm volatile("cp.async.commit_group;" ::: "memory");
}
__device__ __forceinline__ void ldsm4(uint32_t* r, uint32_t addr) {
    asm volatile("ldmatrix.sync.aligned.m8n8.x4.shared.b16 {%0,%1,%2,%3}, [%4];"
        : "=r"(r[0]), "=r"(r[1]), "=r"(r[2]), "=r"(r[3]) : "r"(addr));
}
__device__ __forceinline__ void ldsm4t(uint32_t* r, uint32_t addr) {
    asm volatile("ldmatrix.sync.aligned.m8n8.x4.trans.shared.b16 {%0,%1,%2,%3}, [%4];"
        : "=r"(r[0]), "=r"(r[1]), "=r"(r[2]), "=r"(r[3]) : "r"(addr));
}
__device__ __forceinline__ void mma_f16(float* c, const uint32_t* a, const uint32_t* b) {
    asm volatile("mma.sync.aligned.m16n8k16.row.col.f32.f16.f16.f32 "
        "{%0,%1,%2,%3}, {%4,%5,%6,%7}, {%8,%9}, {%0,%1,%2,%3};"
        : "+f"(c[0]), "+f"(c[1]), "+f"(c[2]), "+f"(c[3])
        : "r"(a[0]), "r"(a[1]), "r"(a[2]), "r"(a[3]), "r"(b[0]), "r"(b[1]));
}

// ---------------------------------------------------------------------------
// Prep: fused f32 -> f16 conversion of query, W_qv, W_out (natural layouts)
// ---------------------------------------------------------------------------
#define CVT_N4 ((MROWS * DFEAT + DFEAT * NQV + DFEAT * DFEAT) / 4)   // 1.75M float4s
__global__ void cvt_all_kernel(const float4* __restrict__ q,
                               const float4* __restrict__ wqv,
                               const float4* __restrict__ wout) {
    int i = blockIdx.x * 256 + threadIdx.x;
    if (i >= CVT_N4) return;
    const float4* src; __half* dst; int off;
    if (i < MROWS * DFEAT / 4)       { src = q;    dst = g_qh;    off = i; }
    else if (i < (MROWS * DFEAT + DFEAT * NQV) / 4)
                                      { src = wqv;  dst = g_wqvh;  off = i - MROWS * DFEAT / 4; }
    else                              { src = wout; dst = g_wouth; off = i - (MROWS * DFEAT + DFEAT * NQV) / 4; }
    float4 v = src[off];
    __half2 h0 = __floats2half2_rn(v.x, v.y);
    __half2 h1 = __floats2half2_rn(v.z, v.w);
    *(uint2*)(dst + (size_t)off * 4) = make_uint2(*(uint32_t*)&h0, *(uint32_t*)&h1);
}

// pack W2_0 [1024,84], W2_1 [1024,164] -> g_w2h [1024,256] natural layout, fp16
__global__ void pack_w2h_kernel(const float* __restrict__ w20, const float* __restrict__ w21) {
    int idx = blockIdx.x * 256 + threadIdx.x;    // 0 .. 1024*256-1
    int k = idx >> 8, n = idx & 255;
    float v = 0.f;
    if (n < 84)       v = w20[k * 84 + n];
    else if (n < 248) v = w21[k * 164 + (n - 84)];
    g_w2h[idx] = __float2half_rn(v);
}

// ---------------------------------------------------------------------------
// fp16 mma.sync GEMM: C[M,N] = A[M,K] @ B[K,N], fp32 accumulate.
// A row-major fp16, B row-major (K-major) fp16 — B fragments via ldmatrix.trans.
// Block tile TBM x 128, BK=64, 3-stage cp.async, 8 warps (TWM x 32 each).
// __launch_bounds__(256,2) -> 2 CTAs/SM.
// MODE 0: fp32 to Cq. MODE 1 (qv split): col<DFEAT -> relu fp16 Cq; else fp32 Cv.
// ---------------------------------------------------------------------------
#define BK 64
#define NSTAGE 3

template <int TBM, int TWM, int MODE>
__global__ __launch_bounds__(256, 2)
void hgemm_kernel(const __half* __restrict__ A, int lda,
                  const __half* __restrict__ B, int ldb,
                  void* __restrict__ Cq, void* __restrict__ Cv,
                  int ldc, int K) {
    constexpr int ATB = TBM * BK * 2;           // A tile bytes (rows of 128B)
    constexpr int BTB = BK * 128 * 2;           // B tile bytes: 64 rows x 256B
    constexpr int STB = ATB + BTB;
    constexpr int MT  = TWM / 16;
    constexpr int WM_CNT = TBM / TWM;

    extern __shared__ char smem[];
    const uint32_t sb = smem_u32(smem);
    const int tid = threadIdx.x;
    const int lane = tid & 31, warp = tid >> 5;
    const int wm = (warp & (WM_CNT - 1)) * TWM;
    const int wn = (warp / WM_CNT) * 32;
    const int mBase = blockIdx.y * TBM;
    const int nBase = blockIdx.x * 128;
    const int lrow = lane & 7, mat = lane >> 3;

    const __half* Abase = A + (size_t)mBase * lda;
    const __half* Bbase = B + nBase;
    const int NIT = K / BK;

    float acc[MT][4][4];
#pragma unroll
    for (int i = 0; i < MT; i++)
#pragma unroll
        for (int j = 0; j < 4; j++)
#pragma unroll
            for (int l = 0; l < 4; l++) acc[i][j][l] = 0.f;

    // A: TBM rows x 8 chunks(16B), swizzle ch ^= r&7
    // B: 64 k-rows x 16 chunks(16B) (256B rows), swizzle ch ^= r&7 (low 3 bits)
    auto load_tile = [&](uint32_t stageBase, const __half* Ag, const __half* Bg) {
#pragma unroll
        for (int i = 0; i < TBM / 32; i++) {
            int cid = tid + i * 256;
            int r = cid >> 3, ch = cid & 7;
            uint32_t dst = stageBase + r * 128 + ((ch ^ (r & 7)) << 4);
            cp_async16(dst, Ag + (size_t)r * lda + ch * 8);
        }
        uint32_t bB = stageBase + ATB;
#pragma unroll
        for (int i = 0; i < 4; i++) {
            int cid = tid + i * 256;
            int r = cid >> 4, ch = cid & 15;
            uint32_t dst = bB + r * 256 + ((ch ^ (r & 7)) << 4);
            cp_async16(dst, Bg + (size_t)r * ldb + ch * 8);
        }
    };

    load_tile(sb, Abase, Bbase); cp_commit();
    load_tile(sb + STB, Abase + BK, Bbase + (size_t)BK * ldb); cp_commit();

    int arow[MT];
#pragma unroll
    for (int mt = 0; mt < MT; mt++) arow[mt] = wm + mt * 16 + ((mat & 1) << 3) + lrow;
    const int achunk = (mat >> 1);       // + 2*kk
    const int cbase = (wn >> 3) + (mat >> 1);   // B n-chunk for this lane's matrix

    for (int it = 0; it < NIT; it++) {
        int s = it - (it / 3) * 3;
        asm volatile("cp.async.wait_group 1;" ::: "memory");
        __syncthreads();

        uint32_t aTile = sb + s * STB;
        uint32_t bTile = aTile + ATB;

#pragma unroll
        for (int kk = 0; kk < 4; kk++) {         // 4 x k16 per BK=64
            uint32_t af[MT][4], bf[4][2];
#pragma unroll
            for (int mt = 0; mt < MT; mt++) {
                int ch = 2 * kk + achunk;
                uint32_t addr = aTile + arow[mt] * 128 + ((ch ^ (arow[mt] & 7)) << 4);
                ldsm4(af[mt], addr);
            }
            // B via ldmatrix.trans: matrix m = lane>>3: k-half = m&1, n-tile = m>>1
            {
                int kb = kk * 16 + ((mat & 1) << 3) + lrow;
                uint32_t rowAddr = bTile + kb * 256;
                int kx = kb & 7;
                uint32_t a0 = rowAddr + (((cbase)     ^ kx) << 4);
                uint32_t a1 = rowAddr + (((cbase + 2) ^ kx) << 4);
                uint32_t r[4];
                ldsm4t(r, a0);
                bf[0][0] = r[0]; bf[0][1] = r[1]; bf[1][0] = r[2]; bf[1][1] = r[3];
                ldsm4t(r, a1);
                bf[2][0] = r[0]; bf[2][1] = r[1]; bf[3][0] = r[2]; bf[3][1] = r[3];
            }
#pragma unroll
            for (int mt = 0; mt < MT; mt++)
#pragma unroll
                for (int nt = 0; nt < 4; nt++)
                    mma_f16(acc[mt][nt], af[mt], bf[nt]);
        }

        if (it + 2 < NIT) {
            int sw = (it + 2) - ((it + 2) / 3) * 3;
            load_tile(sb + sw * STB, Abase + (it + 2) * BK,
                      Bbase + (size_t)(it + 2) * BK * ldb);
        }
        cp_commit();   // keep group count uniform
    }

    // epilogue
    const int g = lane >> 2, tig = lane & 3;
#pragma unroll
    for (int mt = 0; mt < MT; mt++) {
#pragma unroll
        for (int nt = 0; nt < 4; nt++) {
            int row = mBase + wm + mt * 16 + g;
            int col = nBase + wn + nt * 8 + tig * 2;
            if (MODE == 0) {
                float* C = (float*)Cq;
                *(float2*)(C + (size_t)row * ldc + col) =
                    make_float2(acc[mt][nt][0], acc[mt][nt][1]);
                *(float2*)(C + (size_t)(row + 8) * ldc + col) =
                    make_float2(acc[mt][nt][2], acc[mt][nt][3]);
            } else {
                if (col < DFEAT) {
                    __half* Q = (__half*)Cq;
                    __half2 h0 = __floats2half2_rn(fmaxf(acc[mt][nt][0], 0.f),
                                                   fmaxf(acc[mt][nt][1], 0.f));
                    __half2 h1 = __floats2half2_rn(fmaxf(acc[mt][nt][2], 0.f),
                                                   fmaxf(acc[mt][nt][3], 0.f));
                    *(__half2*)(Q + (size_t)row * DFEAT + col) = h0;
                    *(__half2*)(Q + (size_t)(row + 8) * DFEAT + col) = h1;
                } else {
                    float* V = (float*)Cv;
                    int vc = col - DFEAT;
                    *(float2*)(V + (size_t)row * DFEAT + vc) =
                        make_float2(acc[mt][nt][0], acc[mt][nt][1]);
                    *(float2*)(V + (size_t)(row + 8) * DFEAT + vc) =
                        make_float2(acc[mt][nt][2], acc[mt][nt][3]);
                }
            }
        }
    }
}

// ---------------------------------------------------------------------------
// Fused softmax: per (row, head) compute both scale softmaxes and emit the
// merged 41-tap window  w[j] = sw1*attn1[j] + sw0*attn0[j-10] (j-10 in [0,21))
// ---------------------------------------------------------------------------
__global__ void softmax_fused_kernel(const float* __restrict__ sweights) {
    int idx = blockIdx.x * 256 + threadIdx.x;
    if (idx >= MROWS * 4) return;
    int row = idx >> 2, h = idx & 3;
    const float* lp = g_logits + (size_t)row * NLOGPAD;
    const int b0 = h * 21;
    const int b1 = 84 + h * 41;

    float m0 = -1e30f, m1 = -1e30f;
    for (int c = 0; c < C0; c++) m0 = fmaxf(m0, lp[b0 + c]);
    for (int c = 0; c < C1; c++) m1 = fmaxf(m1, lp[b1 + c]);
    float s0 = 0.f, s1 = 0.f;
    for (int c = 0; c < C0; c++) s0 += expf(lp[b0 + c] - m0);
    for (int c = 0; c < C1; c++) s1 += expf(lp[b1 + c] - m1);

    float w0 = sweights[0], w1 = sweights[1];
    float mm = fmaxf(w0, w1);
    float e0 = expf(w0 - mm), e1 = expf(w1 - mm);
    float sden = 1.f / (e0 + e1);
    float inv0 = e0 * sden / s0;
    float inv1 = e1 * sden / s1;

    float* ap = g_attn + (size_t)row * WSTRIDE + h * 44;
    for (int j = 0; j < C1; j++) {
        float w = expf(lp[b1 + j] - m1) * inv1;
        if (j >= 10 && j < 31) w += expf(lp[b0 + j - 10] - m0) * inv0;
        ap[j] = w;
    }
}

// ---------------------------------------------------------------------------
// Sliding-window weighted sum (single fused 41-tap window) -> g_xh fp16
// Each thread: 4 consecutive tl x float4 d; one LDS.128 per shared v-row.
// ---------------------------------------------------------------------------
__global__ __launch_bounds__(256) void attn_apply_kernel() {
    __shared__ float vs[72][128];
    __shared__ float as_[32][44];

    const int t0 = blockIdx.x * 32;
    const int by = blockIdx.y;       // 0..7 : 128-wide D slice (head = by>>1)
    const int b  = blockIdx.z;
    const int h  = by >> 1;
    const int coff = by * 128;
    const int tid = threadIdx.x;

#pragma unroll
    for (int i = 0; i < 9; i++) {
        int v = tid + i * 256;
        int row = v >> 5;
        int cv = (v & 31) * 4;
        int gt = t0 - 20 + row;
        float4 val = make_float4(0.f, 0.f, 0.f, 0.f);
        if (gt >= 0 && gt < TSEQ)
            val = *(const float4*)(g_v + (size_t)(b * TSEQ + gt) * DFEAT + coff + cv);
        *(float4*)(&vs[row][cv]) = val;
    }
    for (int idx = tid; idx < 32 * 44; idx += 256) {
        int tl = idx / 44, c = idx % 44;
        as_[tl][c] = (c < C1)
            ? g_attn[(size_t)(b * TSEQ + t0 + tl) * WSTRIDE + h * 44 + c] : 0.f;
    }
    __syncthreads();

    const int d4  = (tid & 31) * 4;
    const int tl0 = (tid >> 5) * 4;

    float4 acc[4];
#pragma unroll
    for (int tl = 0; tl < 4; tl++) acc[tl] = make_float4(0.f, 0.f, 0.f, 0.f);

    // v row = t0 + tl0 + tl + (c - 20) - (t0 - 20) = tl0 + tl + c  (c in [0,41))
#pragma unroll
    for (int rr = 0; rr < 44; rr++) {
        float4 v = *(const float4*)(&vs[tl0 + rr][d4]);
#pragma unroll
        for (int tl = 0; tl < 4; tl++) {
            int c = rr - tl;
            if (c >= 0 && c < C1) {
                float w = as_[tl0 + tl][c];
                acc[tl].x += w * v.x; acc[tl].y += w * v.y;
                acc[tl].z += w * v.z; acc[tl].w += w * v.w;
            }
        }
    }

#pragma unroll
    for (int tl = 0; tl < 4; tl++) {
        __half2 h0 = __floats2half2_rn(acc[tl].x, acc[tl].y);
        __half2 h1 = __floats2half2_rn(acc[tl].z, acc[tl].w);
        *(uint2*)(g_xh + (size_t)(b * TSEQ + t0 + tl0 + tl) * DFEAT + coff + d4) =
            make_uint2(*(uint32_t*)&h0, *(uint32_t*)&h1);
    }
}

// ---------------------------------------------------------------------------
// Launch
// ---------------------------------------------------------------------------
extern "C" void kernel_launch(void* const* d_in, const int* in_sizes, int n_in,
                              void* d_out, int out_size) {
    const float* query    = (const float*)d_in[0];
    // d_in[1]=key, d_in[2]=value: unused by reference
    const float* W_qv     = (const float*)d_in[3];
    const float* W2_0     = (const float*)d_in[4];
    const float* W2_1     = (const float*)d_in[5];
    const float* sweights = (const float*)d_in[6];
    const float* W_out    = (const float*)d_in[7];
    float* out = (float*)d_out;

    constexpr int SMEM_128 = NSTAGE * (128 * BK * 2 + BK * 128 * 2);  // 98304
    constexpr int SMEM_64  = NSTAGE * (64 * BK * 2 + BK * 128 * 2);   // 73728
    cudaFuncSetAttribute(hgemm_kernel<128, 64, 1>,
                         cudaFuncAttributeMaxDynamicSharedMemorySize, SMEM_128);
    cudaFuncSetAttribute(hgemm_kernel<128, 64, 0>,
                         cudaFuncAttributeMaxDynamicSharedMemorySize, SMEM_128);
    cudaFuncSetAttribute(hgemm_kernel<64, 32, 0>,
                         cudaFuncAttributeMaxDynamicSharedMemorySize, SMEM_64);

    void *qh_p = nullptr, *wqvh_p = nullptr, *wouth_p = nullptr, *w2h_p = nullptr;
    void *qrelu_p = nullptr, *v_p = nullptr, *logits_p = nullptr, *xh_p = nullptr;
    cudaGetSymbolAddress(&qh_p, g_qh);
    cudaGetSymbolAddress(&wqvh_p, g_wqvh);
    cudaGetSymbolAddress(&wouth_p, g_wouth);
    cudaGetSymbolAddress(&w2h_p, g_w2h);
    cudaGetSymbolAddress(&qrelu_p, g_qrelu);
    cudaGetSymbolAddress(&v_p, g_v);
    cudaGetSymbolAddress(&logits_p, g_logits);
    cudaGetSymbolAddress(&xh_p, g_xh);

    // 1) prep: fused fp32 -> fp16 conversions (natural layouts) + W2 pack
    cvt_all_kernel<<<(CVT_N4 + 255) / 256, 256>>>(
        (const float4*)query, (const float4*)W_qv, (const float4*)W_out);
    pack_w2h_kernel<<<DFEAT * NLOGPAD / 256, 256>>>(W2_0, W2_1);

    // 2) qv = query @ W_qv : q half -> relu fp16 g_qrelu; v half -> fp32 g_v
    hgemm_kernel<128, 64, 1><<<dim3(NQV / 128, MROWS / 128), 256, SMEM_128>>>(
        (const __half*)qh_p, DFEAT, (const __half*)wqvh_p, NQV,
        qrelu_p, v_p, 0, DFEAT);

    // 3) logits = relu(q) @ W2
    hgemm_kernel<64, 32, 0><<<dim3(NLOGPAD / 128, MROWS / 64), 256, SMEM_64>>>(
        (const __half*)qrelu_p, DFEAT, (const __half*)w2h_p, NLOGPAD,
        logits_p, nullptr, NLOGPAD, DFEAT);

    // 4) fused per-head softmax + scale merge -> 41-tap weights
    softmax_fused_kernel<<<(MROWS * 4 + 255) / 256, 256>>>(sweights);

    // 5) sliding-window weighted sum -> g_xh (fp16)
    attn_apply_kernel<<<dim3(TSEQ / 32, 8, BATCH), 256>>>();

    // 6) out = x @ W_out
    hgemm_kernel<128, 64, 0><<<dim3(DFEAT / 128, MROWS / 128), 256, SMEM_128>>>(
        (const __half*)xh_p, DFEAT, (const __half*)wouth_p, DFEAT,
        out, nullptr, DFEAT, DFEAT);
}